// round 13
// baseline (speedup 1.0000x reference)
#include <cuda_runtime.h>
#include <cuda_fp16.h>
#include <math.h>
#include <stdint.h>

// ---------------- problem constants ----------------
#define B_   8
#define H_   32
#define W_   32
#define L_   1024
#define C_   512
#define DI_  1024
#define K_   4
#define N_   16
#define R_   32
#define ML_  (B_ * L_)          // 8192 rows

// ---------------- scratch (device globals) ----------------
__device__ __half g_xnh [(size_t)ML_ * C_];            // layernorm(x)  (half)
__device__ __half g_xzh [(size_t)ML_ * 2 * DI_];       // in_proj out   (half)
__device__ __half g_xch [(size_t)ML_ * DI_];           // conv+silu     (half)
__device__ __half g_xdth[(size_t)B_ * K_ * L_ * 32];   // x_dbl dt-part (half)
__device__ float  g_xbc [(size_t)B_ * K_ * L_ * 32];   // x_dbl B/C     fp32
__device__ __half g_dtsh[(size_t)B_ * K_ * L_ * DI_];  // (bk, t, d)    half
__device__ __half g_ysh [(size_t)B_ * K_ * L_ * DI_];  // (bk, l, d)    half
__device__ __half g_yfh [(size_t)ML_ * DI_];           // pre-out_proj  half
__device__ __half g_wA  [2 * DI_ * C_];                // in_proj_w  half
__device__ __half g_wB  [C_ * DI_];                    // out_proj_w half
__device__ __half g_wX  [K_ * 64 * DI_];               // x_proj_w   half
__device__ __half g_wD  [K_ * DI_ * R_];               // dt_projs_w half

// scan index map: spatial l for direction k at scan step t
__device__ __forceinline__ int map_t(int k, int t) {
    int tt = (k & 2) ? (L_ - 1 - t) : t;
    return (k & 1) ? (((tt & 31) << 5) | (tt >> 5)) : tt;
}

__device__ __forceinline__ uint32_t smem_u32(const void* p) {
    return (uint32_t)__cvta_generic_to_shared(p);
}
__device__ __forceinline__ void ldsm4(uint32_t* r, uint32_t addr) {
    asm volatile("ldmatrix.sync.aligned.m8n8.x4.shared.b16 {%0,%1,%2,%3}, [%4];"
                 : "=r"(r[0]), "=r"(r[1]), "=r"(r[2]), "=r"(r[3]) : "r"(addr));
}
__device__ __forceinline__ void mma16816(float* c, const uint32_t* a, const uint32_t* b) {
    asm volatile("mma.sync.aligned.m16n8k16.row.col.f32.f16.f16.f32 "
                 "{%0,%1,%2,%3}, {%4,%5,%6,%7}, {%8,%9}, {%0,%1,%2,%3};"
                 : "+f"(c[0]), "+f"(c[1]), "+f"(c[2]), "+f"(c[3])
                 : "r"(a[0]), "r"(a[1]), "r"(a[2]), "r"(a[3]), "r"(b[0]), "r"(b[1]));
}
__device__ __forceinline__ void cp16(uint32_t dst, const void* src) {
    asm volatile("cp.async.cg.shared.global [%0], [%1], 16;\n" :: "r"(dst), "l"(src));
}
#define CP_COMMIT() asm volatile("cp.async.commit_group;\n" ::: "memory")
#define CP_WAIT2()  asm volatile("cp.async.wait_group 2;\n" ::: "memory")
#define CP_WAIT1()  asm volatile("cp.async.wait_group 1;\n" ::: "memory")
#define CP_WAIT0()  asm volatile("cp.async.wait_group 0;\n" ::: "memory")

// ---------------- packed f32x2 helpers (sm_100+) ----------------
typedef unsigned long long u64t;
__device__ __forceinline__ u64t pack2(float lo, float hi) {
    u64t r; asm("mov.b64 %0, {%1, %2};" : "=l"(r) : "f"(lo), "f"(hi)); return r;
}
__device__ __forceinline__ void unpack2(float& lo, float& hi, u64t v) {
    asm("mov.b64 {%0, %1}, %2;" : "=f"(lo), "=f"(hi) : "l"(v));
}
__device__ __forceinline__ u64t mul2(u64t a, u64t b) {
    u64t r; asm("mul.rn.f32x2 %0, %1, %2;" : "=l"(r) : "l"(a), "l"(b)); return r;
}
__device__ __forceinline__ u64t fma2(u64t a, u64t b, u64t c) {
    u64t r; asm("fma.rn.f32x2 %0, %1, %2, %3;" : "=l"(r) : "l"(a), "l"(b), "l"(c)); return r;
}

// ---------------- weight fp32 -> fp16 convert (split for profiler slotting) --------
__global__ void __launch_bounds__(256) convertA_kernel(const float* __restrict__ ipw) {
    int i = blockIdx.x * 256 + threadIdx.x;
    if (i < 2 * DI_ * C_) g_wA[i] = __float2half_rn(ipw[i]);
}
__global__ void __launch_bounds__(256) convertR_kernel(const float* __restrict__ opw,
                                                       const float* __restrict__ xpw,
                                                       const float* __restrict__ dtw) {
    int i = blockIdx.x * 256 + threadIdx.x;
    if (i < C_ * DI_)        g_wB[i] = __float2half_rn(opw[i]);
    if (i < K_ * 64 * DI_)   g_wX[i] = __float2half_rn(xpw[i]);
    if (i < K_ * DI_ * R_)   g_wD[i] = __float2half_rn(dtw[i]);
}

// ---------------- input layernorm (row = 512) -> half ----------------
__global__ void __launch_bounds__(128) ln_kernel(const float* __restrict__ x,
                                                 const float* __restrict__ w,
                                                 const float* __restrict__ bb) {
    int bl = blockIdx.x;
    int tid = threadIdx.x;
    const float* xr = x + (size_t)bl * C_;
    float4 v = *(const float4*)(xr + tid * 4);
    float s = v.x + v.y + v.z + v.w;
    float q = v.x * v.x + v.y * v.y + v.z * v.z + v.w * v.w;
#pragma unroll
    for (int o = 16; o; o >>= 1) {
        s += __shfl_xor_sync(0xffffffffu, s, o);
        q += __shfl_xor_sync(0xffffffffu, q, o);
    }
    __shared__ float shs[4], shq[4];
    if ((tid & 31) == 0) { shs[tid >> 5] = s; shq[tid >> 5] = q; }
    __syncthreads();
    float S = shs[0] + shs[1] + shs[2] + shs[3];
    float Q = shq[0] + shq[1] + shq[2] + shq[3];
    float mu  = S * (1.0f / C_);
    float var = Q * (1.0f / C_) - mu * mu;
    float rs  = rsqrtf(var + 1e-5f);
    float4 wv = *(const float4*)(w + tid * 4);
    float4 bv = *(const float4*)(bb + tid * 4);
    float o0 = (v.x - mu) * rs * wv.x + bv.x;
    float o1 = (v.y - mu) * rs * wv.y + bv.y;
    float o2 = (v.z - mu) * rs * wv.z + bv.z;
    float o3 = (v.w - mu) * rs * wv.w + bv.w;
    __half* dst = g_xnh + (size_t)bl * C_ + tid * 4;
    *(__half2*)(dst)     = __floats2half2_rn(o0, o1);
    *(__half2*)(dst + 2) = __floats2half2_rn(o2, o3);
}

// ---------------- tensor-core NT hgemm, 3-stage cp.async (dynamic smem) ------------
// smem: As[3][128][40], Bs[3][128][40]  -> 60 KB dynamic
template <int MODE>
__global__ void __launch_bounds__(256) hgemm_nt(const float* __restrict__ resid,
                                                float* __restrict__ Cout) {
    constexpr int Kd = (MODE == 0) ? C_ : DI_;
    constexpr int Nd = (MODE == 0) ? 2 * DI_ : C_;
    constexpr int NIT = Kd / 32;
    const __half* A = (MODE == 0) ? g_xnh : g_yfh;
    const __half* Wh = (MODE == 0) ? g_wA : g_wB;

    extern __shared__ __half sh[];
    __half (*As)[128][40] = (__half (*)[128][40])sh;
    __half (*Bs)[128][40] = (__half (*)[128][40])(sh + 3 * 128 * 40);

    int tid = threadIdx.x;
    int lane = tid & 31, wid = tid >> 5;
    int wm = wid & 1, wn = wid >> 1;
    int m0 = blockIdx.y * 128, n0 = blockIdx.x * 128;

    float c[4][4][4];
#pragma unroll
    for (int i = 0; i < 4; ++i)
#pragma unroll
        for (int j = 0; j < 4; ++j)
#pragma unroll
            for (int e = 0; e < 4; ++e) c[i][j][e] = 0.0f;

    int lrow = tid >> 2;
    int lseg = (tid & 3) * 8;
    const __half* pa0 = A + (size_t)(m0 + lrow) * Kd + lseg;
    const __half* pa1 = A + (size_t)(m0 + 64 + lrow) * Kd + lseg;
    const __half* pb0 = Wh + (size_t)(n0 + lrow) * Kd + lseg;
    const __half* pb1 = Wh + (size_t)(n0 + 64 + lrow) * Kd + lseg;

    // prologue: stages 0 and 1
#pragma unroll
    for (int p = 0; p < 2; ++p) {
        int k0 = p * 32;
        cp16(smem_u32(&As[p][lrow][lseg]), pa0 + k0);
        cp16(smem_u32(&As[p][64 + lrow][lseg]), pa1 + k0);
        cp16(smem_u32(&Bs[p][lrow][lseg]), pb0 + k0);
        cp16(smem_u32(&Bs[p][64 + lrow][lseg]), pb1 + k0);
        CP_COMMIT();
    }

    for (int it = 0; it < NIT; ++it) {
        if (it + 2 < NIT) {
            int s = (it + 2) % 3;
            int k0 = (it + 2) * 32;
            cp16(smem_u32(&As[s][lrow][lseg]), pa0 + k0);
            cp16(smem_u32(&As[s][64 + lrow][lseg]), pa1 + k0);
            cp16(smem_u32(&Bs[s][lrow][lseg]), pb0 + k0);
            cp16(smem_u32(&Bs[s][64 + lrow][lseg]), pb1 + k0);
        }
        CP_COMMIT();           // empty groups at tail keep accounting uniform
        CP_WAIT2();            // stage `it` complete
        __syncthreads();
        int s = it % 3;
#pragma unroll
        for (int kk = 0; kk < 2; ++kk) {
            uint32_t a[4][4];
#pragma unroll
            for (int mi = 0; mi < 4; ++mi) {
                uint32_t addr = smem_u32(&As[s][wm * 64 + mi * 16 + (lane & 15)]
                                              [kk * 16 + ((lane >> 4) << 3)]);
                ldsm4(a[mi], addr);
            }
            uint32_t bfr[4][2];
#pragma unroll
            for (int nj = 0; nj < 2; ++nj) {
                int n_off = (lane & 7) + ((lane >> 4) << 3);
                int kh = ((lane >> 3) & 1) * 8;
                uint32_t addr = smem_u32(&Bs[s][wn * 32 + nj * 16 + n_off][kk * 16 + kh]);
                uint32_t t4[4];
                ldsm4(t4, addr);
                bfr[2 * nj][0] = t4[0]; bfr[2 * nj][1] = t4[1];
                bfr[2 * nj + 1][0] = t4[2]; bfr[2 * nj + 1][1] = t4[3];
            }
#pragma unroll
            for (int mi = 0; mi < 4; ++mi)
#pragma unroll
                for (int ni = 0; ni < 4; ++ni)
                    mma16816(c[mi][ni], a[mi], bfr[ni]);
        }
        __syncthreads();
    }

#pragma unroll
    for (int mi = 0; mi < 4; ++mi) {
#pragma unroll
        for (int ni = 0; ni < 4; ++ni) {
            int r0 = m0 + wm * 64 + mi * 16 + (lane >> 2);
            int cc = n0 + wn * 32 + ni * 8 + ((lane & 3) << 1);
            if (MODE == 0) {
                *(__half2*)(g_xzh + (size_t)r0 * Nd + cc) =
                    __floats2half2_rn(c[mi][ni][0], c[mi][ni][1]);
                *(__half2*)(g_xzh + (size_t)(r0 + 8) * Nd + cc) =
                    __floats2half2_rn(c[mi][ni][2], c[mi][ni][3]);
            } else {
                float2 ra = *(const float2*)(resid + (size_t)r0 * Nd + cc);
                float2 rb = *(const float2*)(resid + (size_t)(r0 + 8) * Nd + cc);
                float2 oa = make_float2(c[mi][ni][0] + ra.x, c[mi][ni][1] + ra.y);
                float2 ob = make_float2(c[mi][ni][2] + rb.x, c[mi][ni][3] + rb.y);
                *(float2*)(Cout + (size_t)r0 * Nd + cc) = oa;
                *(float2*)(Cout + (size_t)(r0 + 8) * Nd + cc) = ob;
            }
        }
    }
}

// ---------------- depthwise 3x3 conv + bias + silu: sliding-window row kernel ----
// grid = (h, channel-half, b); 256 threads; thread handles 2 channels across w.
__global__ void __launch_bounds__(256) conv_kernel(const float* __restrict__ cw,
                                                   const float* __restrict__ cb) {
    int h = blockIdx.x, b = blockIdx.z;
    int d = blockIdx.y * 512 + threadIdx.x * 2;

    float wa[9], wb[9];
#pragma unroll
    for (int i = 0; i < 9; ++i) {
        wa[i] = __ldg(cw + d * 9 + i);
        wb[i] = __ldg(cw + (d + 1) * 9 + i);
    }
    float bias0 = __ldg(cb + d), bias1 = __ldg(cb + d + 1);

    const __half2* row[3];
    bool rv[3];
#pragma unroll
    for (int r = 0; r < 3; ++r) {
        int hh = h + r - 1;
        rv[r] = (unsigned)hh < 32u;
        row[r] = (const __half2*)(g_xzh + ((size_t)(b * L_ + ((hh & 31) << 5))) * (2 * DI_) + d);
    }

    float2 c0[3], c1[3], c2[3];
#pragma unroll
    for (int r = 0; r < 3; ++r) {
        c0[r] = make_float2(0.f, 0.f);
        c1[r] = rv[r] ? __half22float2(row[r][0])          : make_float2(0.f, 0.f);
        c2[r] = rv[r] ? __half22float2(row[r][(size_t)DI_]) : make_float2(0.f, 0.f);
    }

    __half2* outp = (__half2*)(g_xch + ((size_t)(b * L_ + (h << 5))) * DI_ + d);
#pragma unroll 4
    for (int w = 0; w < 32; ++w) {
        float a0 = bias0, a1 = bias1;
#pragma unroll
        for (int r = 0; r < 3; ++r) {
            a0 = fmaf(c0[r].x, wa[r * 3 + 0], a0);
            a0 = fmaf(c1[r].x, wa[r * 3 + 1], a0);
            a0 = fmaf(c2[r].x, wa[r * 3 + 2], a0);
            a1 = fmaf(c0[r].y, wb[r * 3 + 0], a1);
            a1 = fmaf(c1[r].y, wb[r * 3 + 1], a1);
            a1 = fmaf(c2[r].y, wb[r * 3 + 2], a1);
        }
        float s0 = a0 / (1.0f + __expf(-a0));
        float s1 = a1 / (1.0f + __expf(-a1));
        outp[(size_t)w * (DI_ / 2)] = __floats2half2_rn(s0, s1);

        int wn = w + 2;
        bool wv = wn < 32;
#pragma unroll
        for (int r = 0; r < 3; ++r) {
            c0[r] = c1[r];
            c1[r] = c2[r];
            c2[r] = (rv[r] && wv) ? __half22float2(row[r][(size_t)wn * DI_])
                                  : make_float2(0.f, 0.f);
        }
    }
}

// ---------------- x_dbl via tensor cores, cp.async double-buffered ----------------
// epilogue splits: cols 0:32 (dt ranks) -> half g_xdth; cols 32:64 (B/C) -> fp32 g_xbc
__global__ void __launch_bounds__(256) xdbl_kernel() {
    int k = blockIdx.y, b = blockIdx.z;
    int t0 = blockIdx.x * 128;
    int bk = b * K_ + k;

    __shared__ __half As[2][128][40];
    __shared__ __half Bs[2][64][40];

    int tid = threadIdx.x;
    int lane = tid & 31, wid = tid >> 5;
    int wm = wid & 3, wn = wid >> 2;

    const __half* xcb = g_xch + (size_t)b * L_ * DI_;
    const __half* Wh = g_wX + (size_t)k * 64 * DI_;

    float c[2][4][4];
#pragma unroll
    for (int i = 0; i < 2; ++i)
#pragma unroll
        for (int j = 0; j < 4; ++j)
#pragma unroll
            for (int e = 0; e < 4; ++e) c[i][j][e] = 0.0f;

    int lrow = tid >> 2;
    int lseg = (tid & 3) * 8;
    int lsp0 = map_t(k, t0 + lrow);
    int lsp1 = map_t(k, t0 + 64 + lrow);
    const __half* pa0 = xcb + (size_t)lsp0 * DI_ + lseg;
    const __half* pa1 = xcb + (size_t)lsp1 * DI_ + lseg;
    int brow = tid >> 2;
    int bseg = (tid & 3) * 8;
    const __half* pbb = Wh + (size_t)brow * DI_ + bseg;

    {
        cp16(smem_u32(&As[0][lrow][lseg]), pa0);
        cp16(smem_u32(&As[0][64 + lrow][lseg]), pa1);
        cp16(smem_u32(&Bs[0][brow][bseg]), pbb);
        CP_COMMIT();
    }

    for (int it = 0; it < DI_ / 32; ++it) {
        if (it + 1 < DI_ / 32) {
            int s = (it + 1) & 1;
            int dk = (it + 1) * 32;
            cp16(smem_u32(&As[s][lrow][lseg]), pa0 + dk);
            cp16(smem_u32(&As[s][64 + lrow][lseg]), pa1 + dk);
            cp16(smem_u32(&Bs[s][brow][bseg]), pbb + dk);
            CP_COMMIT();
            CP_WAIT1();
        } else {
            CP_WAIT0();
        }
        __syncthreads();
        int s = it & 1;
#pragma unroll
        for (int kk = 0; kk < 2; ++kk) {
            uint32_t a[2][4];
#pragma unroll
            for (int mi = 0; mi < 2; ++mi) {
                uint32_t addr = smem_u32(&As[s][wm * 32 + mi * 16 + (lane & 15)]
                                              [kk * 16 + ((lane >> 4) << 3)]);
                ldsm4(a[mi], addr);
            }
            uint32_t bfr[4][2];
#pragma unroll
            for (int nj = 0; nj < 2; ++nj) {
                int n_off = (lane & 7) + ((lane >> 4) << 3);
                int kh = ((lane >> 3) & 1) * 8;
                uint32_t addr = smem_u32(&Bs[s][wn * 32 + nj * 16 + n_off][kk * 16 + kh]);
                uint32_t t4[4];
                ldsm4(t4, addr);
                bfr[2 * nj][0] = t4[0]; bfr[2 * nj][1] = t4[1];
                bfr[2 * nj + 1][0] = t4[2]; bfr[2 * nj + 1][1] = t4[3];
            }
#pragma unroll
            for (int mi = 0; mi < 2; ++mi)
#pragma unroll
                for (int ni = 0; ni < 4; ++ni)
                    mma16816(c[mi][ni], a[mi], bfr[ni]);
        }
        __syncthreads();
    }

#pragma unroll
    for (int mi = 0; mi < 2; ++mi) {
#pragma unroll
        for (int ni = 0; ni < 4; ++ni) {
            int r0 = wm * 32 + mi * 16 + (lane >> 2);
            int cc = ni * 8 + ((lane & 3) << 1);   // 0..31 within the warp's half
            if (wn == 0) {
                __half* dst = g_xdth + ((size_t)bk * L_ + t0 + r0) * 32 + cc;
                *(__half2*)dst = __floats2half2_rn(c[mi][ni][0], c[mi][ni][1]);
                __half* dst2 = g_xdth + ((size_t)bk * L_ + t0 + r0 + 8) * 32 + cc;
                *(__half2*)dst2 = __floats2half2_rn(c[mi][ni][2], c[mi][ni][3]);
            } else {
                float* dst = g_xbc + ((size_t)bk * L_ + t0 + r0) * 32 + cc;
                *(float2*)dst = make_float2(c[mi][ni][0], c[mi][ni][1]);
                float* dst2 = g_xbc + ((size_t)bk * L_ + t0 + r0 + 8) * 32 + cc;
                *(float2*)dst2 = make_float2(c[mi][ni][2], c[mi][ni][3]);
            }
        }
    }
}

// ---------------- dts via tensor cores: [L x DI x 32] per bk + softplus ----------
__global__ void __launch_bounds__(256) dts_kernel(const float* __restrict__ dtb) {
    int bk = blockIdx.z;
    int k = bk & 3;
    int t0 = blockIdx.y * 128, d0 = blockIdx.x * 128;

    __shared__ __half As[128][40];
    __shared__ __half Bs[128][40];

    int tid = threadIdx.x;
    int lane = tid & 31, wid = tid >> 5;
    int wm = wid & 1, wn = wid >> 1;

#pragma unroll
    for (int it2 = 0; it2 < 2; ++it2) {
        int idx = tid + it2 * 256;
        int row = idx >> 2;
        int seg = (idx & 3) * 8;
        cp16(smem_u32(&As[row][seg]),
             g_xdth + ((size_t)bk * L_ + t0 + row) * 32 + seg);
        cp16(smem_u32(&Bs[row][seg]),
             g_wD + ((size_t)(k * DI_ + d0 + row)) * R_ + seg);
    }
    CP_COMMIT();
    CP_WAIT0();
    __syncthreads();

    float c[4][4][4];
#pragma unroll
    for (int i = 0; i < 4; ++i)
#pragma unroll
        for (int j = 0; j < 4; ++j)
#pragma unroll
            for (int e = 0; e < 4; ++e) c[i][j][e] = 0.0f;

#pragma unroll
    for (int kk = 0; kk < 2; ++kk) {
        uint32_t a[4][4];
#pragma unroll
        for (int mi = 0; mi < 4; ++mi) {
            uint32_t addr = smem_u32(&As[wm * 64 + mi * 16 + (lane & 15)]
                                       [kk * 16 + ((lane >> 4) << 3)]);
            ldsm4(a[mi], addr);
        }
        uint32_t bfr[4][2];
#pragma unroll
        for (int nj = 0; nj < 2; ++nj) {
            int n_off = (lane & 7) + ((lane >> 4) << 3);
            int kh = ((lane >> 3) & 1) * 8;
            uint32_t addr = smem_u32(&Bs[wn * 32 + nj * 16 + n_off][kk * 16 + kh]);
            uint32_t t4[4];
            ldsm4(t4, addr);
            bfr[2 * nj][0] = t4[0]; bfr[2 * nj][1] = t4[1];
            bfr[2 * nj + 1][0] = t4[2]; bfr[2 * nj + 1][1] = t4[3];
        }
#pragma unroll
        for (int mi = 0; mi < 4; ++mi)
#pragma unroll
            for (int ni = 0; ni < 4; ++ni)
                mma16816(c[mi][ni], a[mi], bfr[ni]);
    }

#pragma unroll
    for (int mi = 0; mi < 4; ++mi) {
#pragma unroll
        for (int ni = 0; ni < 4; ++ni) {
            int r0 = t0 + wm * 64 + mi * 16 + (lane >> 2);
            int cc = d0 + wn * 32 + ni * 8 + ((lane & 3) << 1);
            float b0 = __ldg(dtb + k * DI_ + cc);
            float b1 = __ldg(dtb + k * DI_ + cc + 1);
            float v0 = c[mi][ni][0] + b0, v1 = c[mi][ni][1] + b1;
            float v2 = c[mi][ni][2] + b0, v3 = c[mi][ni][3] + b1;
            float s0 = fmaxf(v0, 0.0f) + __logf(1.0f + __expf(-fabsf(v0)));
            float s1 = fmaxf(v1, 0.0f) + __logf(1.0f + __expf(-fabsf(v1)));
            float s2 = fmaxf(v2, 0.0f) + __logf(1.0f + __expf(-fabsf(v2)));
            float s3 = fmaxf(v3, 0.0f) + __logf(1.0f + __expf(-fabsf(v3)));
            *(__half2*)(g_dtsh + ((size_t)bk * L_ + r0) * DI_ + cc) =
                __floats2half2_rn(s0, s1);
            *(__half2*)(g_dtsh + ((size_t)bk * L_ + r0 + 8) * DI_ + cc) =
                __floats2half2_rn(s2, s3);
        }
    }
}

// ---------------- selective scan: packed f32x2 + integer-A fast path (R10 exact) ----
// thread = (b, k, d); 128 threads/block, 256 blocks (2 co-resident blocks/SM).
__global__ void __launch_bounds__(128) scan_kernel(const float* __restrict__ A_logs,
                                                   const float* __restrict__ Ds) {
    int b = blockIdx.z, k = blockIdx.y;
    int d = blockIdx.x * 128 + threadIdx.x;
    int bk = b * K_ + k;
    int row = k * DI_ + d;

    float An[N_];
#pragma unroll
    for (int n = 0; n < N_; ++n) An[n] = -__expf(A_logs[(size_t)row * N_ + n]);
    float A1 = An[0];
    bool fast = true;
#pragma unroll
    for (int n = 1; n < N_; ++n)
        fast = fast && (fabsf(An[n] - (float)(n + 1) * A1) <= 1e-4f * fabsf(An[n]));

    float Dv = Ds[row];
    u64t h2[8];
#pragma unroll
    for (int j = 0; j < 8; ++j) h2[j] = 0ull;

    const float* xd = g_xbc + (size_t)bk * L_ * 32;
    const __half* dtp = g_dtsh + (size_t)bk * L_ * DI_ + d;
    __half* ysk = g_ysh + (size_t)bk * L_ * DI_ + d;
    const __half* up = g_xch + (size_t)b * L_ * DI_ + d;

    __shared__ u64t sbc[64][16];   // [tt][pair]: pairs 0..7 = B, 8..15 = C

    float ubuf[2], dtbuf[2];
    ubuf[0]  = __half2float(__ldg(up + (size_t)map_t(k, 0) * DI_));
    dtbuf[0] = __half2float(__ldg(dtp));
    ubuf[1]  = __half2float(__ldg(up + (size_t)map_t(k, 1) * DI_));
    dtbuf[1] = __half2float(__ldg(dtp + DI_));

    for (int t0 = 0; t0 < L_; t0 += 64) {
        __syncthreads();
#pragma unroll
        for (int i = 0; i < 8; ++i) {
            int p = threadIdx.x + i * 128;       // 0..1023
            int tt = p >> 4, c2 = p & 15;
            float2 v = *(const float2*)(xd + (size_t)(t0 + tt) * 32 + 2 * c2);
            sbc[tt][c2] = pack2(v.x, v.y);
        }
        __syncthreads();

        if (fast) {
#pragma unroll 2
            for (int tt = 0; tt < 64; ++tt) {
                int t = t0 + tt;
                float u  = ubuf[t & 1];
                float dt = dtbuf[t & 1];
                int tn = t + 2;
                if (tn < L_) {
                    ubuf[t & 1]  = __half2float(__ldg(up + (size_t)map_t(k, tn) * DI_));
                    dtbuf[t & 1] = __half2float(__ldg(dtp + (size_t)tn * DI_));
                }
                float du = dt * u;
                u64t du2 = pack2(du, du);
                float e1 = __expf(dt * A1);
                float e2s = e1 * e1;
                u64t dAj = pack2(e1, e2s);
                u64t E2 = pack2(e2s, e2s);
                u64t yacc = pack2(Dv * u, 0.0f);
                const ulonglong2* pr = (const ulonglong2*)&sbc[tt][0];
                u64t bc[16];
#pragma unroll
                for (int jj = 0; jj < 8; ++jj) {
                    ulonglong2 q = pr[jj];
                    bc[2 * jj] = q.x; bc[2 * jj + 1] = q.y;
                }
#pragma unroll
                for (int j = 0; j < 8; ++j) {
                    u64t tmp = mul2(du2, bc[j]);
                    h2[j] = fma2(h2[j], dAj, tmp);
                    yacc = fma2(h2[j], bc[8 + j], yacc);
                    if (j < 7) dAj = mul2(dAj, E2);
                }
                float ylo, yhi;
                unpack2(ylo, yhi, yacc);
                ysk[(size_t)map_t(k, t) * DI_] = __float2half_rn(ylo + yhi);
            }
        } else {
#pragma unroll 2
            for (int tt = 0; tt < 64; ++tt) {
                int t = t0 + tt;
                float u  = ubuf[t & 1];
                float dt = dtbuf[t & 1];
                int tn = t + 2;
                if (tn < L_) {
                    ubuf[t & 1]  = __half2float(__ldg(up + (size_t)map_t(k, tn) * DI_));
                    dtbuf[t & 1] = __half2float(__ldg(dtp + (size_t)tn * DI_));
                }
                float du = dt * u;
                u64t du2 = pack2(du, du);
                u64t yacc = pack2(Dv * u, 0.0f);
                const ulonglong2* pr = (const ulonglong2*)&sbc[tt][0];
                u64t bc[16];
#pragma unroll
                for (int jj = 0; jj < 8; ++jj) {
                    ulonglong2 q = pr[jj];
                    bc[2 * jj] = q.x; bc[2 * jj + 1] = q.y;
                }
#pragma unroll
                for (int j = 0; j < 8; ++j) {
                    u64t dA2 = pack2(__expf(dt * An[2 * j]), __expf(dt * An[2 * j + 1]));
                    u64t tmp = mul2(du2, bc[j]);
                    h2[j] = fma2(h2[j], dA2, tmp);
                    yacc = fma2(h2[j], bc[8 + j], yacc);
                }
                float ylo, yhi;
                unpack2(ylo, yhi, yacc);
                ysk[(size_t)map_t(k, t) * DI_] = __float2half_rn(ylo + yhi);
            }
        }
    }
}

// ---------------- combine 4 dirs + out-layernorm + silu(z) gate -> half ----------------
__global__ void __launch_bounds__(256) combine_kernel(const float* __restrict__ onw,
                                                      const float* __restrict__ onb) {
    int bl = blockIdx.x;
    int b = bl >> 10;
    int l = bl & 1023;
    int tid = threadIdx.x;
    int d0 = tid * 4;

    float a0 = 0.f, a1 = 0.f, a2 = 0.f, a3 = 0.f;
#pragma unroll
    for (int k = 0; k < K_; ++k) {
        const __half* p = g_ysh + (((size_t)(b * K_ + k)) * L_ + l) * DI_ + d0;
        __half2 h01 = *(const __half2*)(p);
        __half2 h23 = *(const __half2*)(p + 2);
        float2 f01 = __half22float2(h01);
        float2 f23 = __half22float2(h23);
        a0 += f01.x; a1 += f01.y; a2 += f23.x; a3 += f23.y;
    }
    float s = a0 + a1 + a2 + a3;
    float q = a0 * a0 + a1 * a1 + a2 * a2 + a3 * a3;
#pragma unroll
    for (int o = 16; o; o >>= 1) {
        s += __shfl_xor_sync(0xffffffffu, s, o);
        q += __shfl_xor_sync(0xffffffffu, q, o);
    }
    __shared__ float shs[8], shq[8];
    if ((tid & 31) == 0) { shs[tid >> 5] = s; shq[tid >> 5] = q; }
    __syncthreads();
    float S = 0.f, Q = 0.f;
#pragma unroll
    for (int i = 0; i < 8; ++i) { S += shs[i]; Q += shq[i]; }
    float mu  = S * (1.0f / DI_);
    float var = Q * (1.0f / DI_) - mu * mu;
    float rs  = rsqrtf(var + 1e-5f);

    float4 wv = *(const float4*)(onw + d0);
    float4 bv = *(const float4*)(onb + d0);
    const __half* zp = g_xzh + (size_t)bl * (2 * DI_) + DI_ + d0;
    float2 z01 = __half22float2(*(const __half2*)(zp));
    float2 z23 = __half22float2(*(const __half2*)(zp + 2));

    float ln0 = (a0 - mu) * rs * wv.x + bv.x;
    float ln1 = (a1 - mu) * rs * wv.y + bv.y;
    float ln2 = (a2 - mu) * rs * wv.z + bv.z;
    float ln3 = (a3 - mu) * rs * wv.w + bv.w;
    float o0 = ln0 * (z01.x / (1.0f + __expf(-z01.x)));
    float o1 = ln1 * (z01.y / (1.0f + __expf(-z01.y)));
    float o2 = ln2 * (z23.x / (1.0f + __expf(-z23.x)));
    float o3 = ln3 * (z23.y / (1.0f + __expf(-z23.y)));

    __half* dst = g_yfh + (size_t)bl * DI_ + d0;
    *(__half2*)(dst)     = __floats2half2_rn(o0, o1);
    *(__half2*)(dst + 2) = __floats2half2_rn(o2, o3);
}

// ---------------- launch ----------------
extern "C" void kernel_launch(void* const* d_in, const int* in_sizes, int n_in,
                              void* d_out, int out_size) {
    const float* x          = (const float*)d_in[0];
    const float* norm_w     = (const float*)d_in[1];
    const float* norm_b     = (const float*)d_in[2];
    const float* in_proj_w  = (const float*)d_in[3];
    const float* conv_w     = (const float*)d_in[4];
    const float* conv_b     = (const float*)d_in[5];
    const float* x_proj_w   = (const float*)d_in[6];
    const float* dt_projs_w = (const float*)d_in[7];
    const float* dt_projs_b = (const float*)d_in[8];
    const float* A_logs     = (const float*)d_in[9];
    const float* Ds         = (const float*)d_in[10];
    const float* out_norm_w = (const float*)d_in[11];
    const float* out_norm_b = (const float*)d_in[12];
    const float* out_proj_w = (const float*)d_in[13];
    float* out = (float*)d_out;

    constexpr int HG_SMEM = 3 * 128 * 40 * 2 * (int)sizeof(__half);  // 61440 B
    static bool attr_set = false;
    if (!attr_set) {
        cudaFuncSetAttribute(hgemm_nt<0>, cudaFuncAttributeMaxDynamicSharedMemorySize, HG_SMEM);
        cudaFuncSetAttribute(hgemm_nt<1>, cudaFuncAttributeMaxDynamicSharedMemorySize, HG_SMEM);
        attr_set = true;
    }

    convertA_kernel<<<(2 * DI_ * C_) / 256, 256>>>(in_proj_w);              // 1
    ln_kernel<<<ML_, 128>>>(x, norm_w, norm_b);                             // 2
    convertR_kernel<<<(C_ * DI_) / 256, 256>>>(out_proj_w, x_proj_w, dt_projs_w); // 3
    hgemm_nt<0><<<dim3((2 * DI_) / 128, ML_ / 128), 256, HG_SMEM>>>(nullptr, nullptr); // 4 (profiled)
    conv_kernel<<<dim3(H_, 2, B_), 256>>>(conv_w, conv_b);                  // 5
    xdbl_kernel<<<dim3(L_ / 128, K_, B_), 256>>>();                         // 6
    dts_kernel<<<dim3(DI_ / 128, L_ / 128, B_ * K_), 256>>>(dt_projs_b);    // 7
    scan_kernel<<<dim3(DI_ / 128, K_, B_), 128>>>(A_logs, Ds);              // 8
    combine_kernel<<<ML_, 256>>>(out_norm_w, out_norm_b);                   // 9
    hgemm_nt<1><<<dim3(C_ / 128, ML_ / 128), 256, HG_SMEM>>>(x, out);       // 10
}

// round 14
// speedup vs baseline: 1.0233x; 1.0233x over previous
#include <cuda_runtime.h>
#include <cuda_fp16.h>
#include <math.h>
#include <stdint.h>

// ---------------- problem constants ----------------
#define B_   8
#define H_   32
#define W_   32
#define L_   1024
#define C_   512
#define DI_  1024
#define K_   4
#define N_   16
#define R_   32
#define ML_  (B_ * L_)          // 8192 rows

// ---------------- scratch (device globals) ----------------
__device__ __half g_xnh [(size_t)ML_ * C_];            // layernorm(x)  (half)
__device__ __half g_xzh [(size_t)ML_ * 2 * DI_];       // in_proj out   (half)
__device__ __half g_xch [(size_t)ML_ * DI_];           // conv+silu     (half)
__device__ __half g_xdth[(size_t)B_ * K_ * L_ * 32];   // x_dbl dt-part (half)
__device__ float  g_xbc [(size_t)B_ * K_ * L_ * 32];   // x_dbl B/C     fp32
__device__ __half g_dtsh[(size_t)B_ * K_ * L_ * DI_];  // (bk, t, d)    half
__device__ __half g_ysh [(size_t)B_ * K_ * L_ * DI_];  // (bk, l, d)    half
__device__ __half g_yfh [(size_t)ML_ * DI_];           // pre-out_proj  half
__device__ __half g_wA  [2 * DI_ * C_];                // in_proj_w  half
__device__ __half g_wB  [C_ * DI_];                    // out_proj_w half
__device__ __half g_wX  [K_ * 64 * DI_];               // x_proj_w   half
__device__ __half g_wD  [K_ * DI_ * R_];               // dt_projs_w half

// scan index map: spatial l for direction k at scan step t
__device__ __forceinline__ int map_t(int k, int t) {
    int tt = (k & 2) ? (L_ - 1 - t) : t;
    return (k & 1) ? (((tt & 31) << 5) | (tt >> 5)) : tt;
}

__device__ __forceinline__ uint32_t smem_u32(const void* p) {
    return (uint32_t)__cvta_generic_to_shared(p);
}
__device__ __forceinline__ void ldsm4(uint32_t* r, uint32_t addr) {
    asm volatile("ldmatrix.sync.aligned.m8n8.x4.shared.b16 {%0,%1,%2,%3}, [%4];"
                 : "=r"(r[0]), "=r"(r[1]), "=r"(r[2]), "=r"(r[3]) : "r"(addr));
}
__device__ __forceinline__ void mma16816(float* c, const uint32_t* a, const uint32_t* b) {
    asm volatile("mma.sync.aligned.m16n8k16.row.col.f32.f16.f16.f32 "
                 "{%0,%1,%2,%3}, {%4,%5,%6,%7}, {%8,%9}, {%0,%1,%2,%3};"
                 : "+f"(c[0]), "+f"(c[1]), "+f"(c[2]), "+f"(c[3])
                 : "r"(a[0]), "r"(a[1]), "r"(a[2]), "r"(a[3]), "r"(b[0]), "r"(b[1]));
}
__device__ __forceinline__ void cp16(uint32_t dst, const void* src) {
    asm volatile("cp.async.cg.shared.global [%0], [%1], 16;\n" :: "r"(dst), "l"(src));
}
#define CP_COMMIT() asm volatile("cp.async.commit_group;\n" ::: "memory")
#define CP_WAIT1()  asm volatile("cp.async.wait_group 1;\n" ::: "memory")
#define CP_WAIT0()  asm volatile("cp.async.wait_group 0;\n" ::: "memory")

// ---------------- packed f32x2 helpers (sm_100+) ----------------
typedef unsigned long long u64t;
__device__ __forceinline__ u64t pack2(float lo, float hi) {
    u64t r; asm("mov.b64 %0, {%1, %2};" : "=l"(r) : "f"(lo), "f"(hi)); return r;
}
__device__ __forceinline__ void unpack2(float& lo, float& hi, u64t v) {
    asm("mov.b64 {%0, %1}, %2;" : "=f"(lo), "=f"(hi) : "l"(v));
}
__device__ __forceinline__ u64t mul2(u64t a, u64t b) {
    u64t r; asm("mul.rn.f32x2 %0, %1, %2;" : "=l"(r) : "l"(a), "l"(b)); return r;
}
__device__ __forceinline__ u64t fma2(u64t a, u64t b, u64t c) {
    u64t r; asm("fma.rn.f32x2 %0, %1, %2, %3;" : "=l"(r) : "l"(a), "l"(b), "l"(c)); return r;
}

// ---------------- prep: weight fp32->fp16 convert + input layernorm, fused --------
// blocks [0, 4096): convert weights.  blocks [4096, 12288): layernorm row (256 thr).
__global__ void __launch_bounds__(256) prep_kernel(const float* __restrict__ ipw,
                                                   const float* __restrict__ opw,
                                                   const float* __restrict__ xpw,
                                                   const float* __restrict__ dtw,
                                                   const float* __restrict__ x,
                                                   const float* __restrict__ nw,
                                                   const float* __restrict__ nb) {
    int bid = blockIdx.x;
    int tid = threadIdx.x;
    if (bid < 4096) {
        int i = bid * 256 + tid;
        g_wA[i] = __float2half_rn(ipw[i]);                       // 2*DI*C = 1048576 exact
        if (i < C_ * DI_)      g_wB[i] = __float2half_rn(opw[i]);
        if (i < K_ * 64 * DI_) g_wX[i] = __float2half_rn(xpw[i]);
        if (i < K_ * DI_ * R_) g_wD[i] = __float2half_rn(dtw[i]);
        return;
    }
    int bl = bid - 4096;
    const float* xr = x + (size_t)bl * C_;
    float2 v = *(const float2*)(xr + tid * 2);
    float s = v.x + v.y;
    float q = v.x * v.x + v.y * v.y;
#pragma unroll
    for (int o = 16; o; o >>= 1) {
        s += __shfl_xor_sync(0xffffffffu, s, o);
        q += __shfl_xor_sync(0xffffffffu, q, o);
    }
    __shared__ float shs[8], shq[8];
    if ((tid & 31) == 0) { shs[tid >> 5] = s; shq[tid >> 5] = q; }
    __syncthreads();
    float S = 0.f, Q = 0.f;
#pragma unroll
    for (int i = 0; i < 8; ++i) { S += shs[i]; Q += shq[i]; }
    float mu  = S * (1.0f / C_);
    float var = Q * (1.0f / C_) - mu * mu;
    float rs  = rsqrtf(var + 1e-5f);
    float2 wv = *(const float2*)(nw + tid * 2);
    float2 bv = *(const float2*)(nb + tid * 2);
    float o0 = (v.x - mu) * rs * wv.x + bv.x;
    float o1 = (v.y - mu) * rs * wv.y + bv.y;
    *(__half2*)(g_xnh + (size_t)bl * C_ + tid * 2) = __floats2half2_rn(o0, o1);
}

// ---------------- tensor-core NT hgemm, cp.async double-buffered (2-stage, R12) ----
template <int MODE>
__global__ void __launch_bounds__(256) hgemm_nt(const float* __restrict__ resid,
                                                float* __restrict__ Cout) {
    constexpr int Kd = (MODE == 0) ? C_ : DI_;
    constexpr int Nd = (MODE == 0) ? 2 * DI_ : C_;
    constexpr int NIT = Kd / 32;
    const __half* A = (MODE == 0) ? g_xnh : g_yfh;
    const __half* Wh = (MODE == 0) ? g_wA : g_wB;

    __shared__ __half As[2][128][40];
    __shared__ __half Bs[2][128][40];

    int tid = threadIdx.x;
    int lane = tid & 31, wid = tid >> 5;
    int wm = wid & 1, wn = wid >> 1;
    int m0 = blockIdx.y * 128, n0 = blockIdx.x * 128;

    float c[4][4][4];
#pragma unroll
    for (int i = 0; i < 4; ++i)
#pragma unroll
        for (int j = 0; j < 4; ++j)
#pragma unroll
            for (int e = 0; e < 4; ++e) c[i][j][e] = 0.0f;

    int lrow = tid >> 2;
    int lseg = (tid & 3) * 8;
    const __half* pa0 = A + (size_t)(m0 + lrow) * Kd + lseg;
    const __half* pa1 = A + (size_t)(m0 + 64 + lrow) * Kd + lseg;
    const __half* pb0 = Wh + (size_t)(n0 + lrow) * Kd + lseg;
    const __half* pb1 = Wh + (size_t)(n0 + 64 + lrow) * Kd + lseg;

    {
        cp16(smem_u32(&As[0][lrow][lseg]), pa0);
        cp16(smem_u32(&As[0][64 + lrow][lseg]), pa1);
        cp16(smem_u32(&Bs[0][lrow][lseg]), pb0);
        cp16(smem_u32(&Bs[0][64 + lrow][lseg]), pb1);
        CP_COMMIT();
    }

    for (int it = 0; it < NIT; ++it) {
        if (it + 1 < NIT) {
            int s = (it + 1) & 1;
            int k0 = (it + 1) * 32;
            cp16(smem_u32(&As[s][lrow][lseg]), pa0 + k0);
            cp16(smem_u32(&As[s][64 + lrow][lseg]), pa1 + k0);
            cp16(smem_u32(&Bs[s][lrow][lseg]), pb0 + k0);
            cp16(smem_u32(&Bs[s][64 + lrow][lseg]), pb1 + k0);
            CP_COMMIT();
            CP_WAIT1();
        } else {
            CP_WAIT0();
        }
        __syncthreads();
        int s = it & 1;
#pragma unroll
        for (int kk = 0; kk < 2; ++kk) {
            uint32_t a[4][4];
#pragma unroll
            for (int mi = 0; mi < 4; ++mi) {
                uint32_t addr = smem_u32(&As[s][wm * 64 + mi * 16 + (lane & 15)]
                                              [kk * 16 + ((lane >> 4) << 3)]);
                ldsm4(a[mi], addr);
            }
            uint32_t bfr[4][2];
#pragma unroll
            for (int nj = 0; nj < 2; ++nj) {
                int n_off = (lane & 7) + ((lane >> 4) << 3);
                int kh = ((lane >> 3) & 1) * 8;
                uint32_t addr = smem_u32(&Bs[s][wn * 32 + nj * 16 + n_off][kk * 16 + kh]);
                uint32_t t4[4];
                ldsm4(t4, addr);
                bfr[2 * nj][0] = t4[0]; bfr[2 * nj][1] = t4[1];
                bfr[2 * nj + 1][0] = t4[2]; bfr[2 * nj + 1][1] = t4[3];
            }
#pragma unroll
            for (int mi = 0; mi < 4; ++mi)
#pragma unroll
                for (int ni = 0; ni < 4; ++ni)
                    mma16816(c[mi][ni], a[mi], bfr[ni]);
        }
        __syncthreads();
    }

#pragma unroll
    for (int mi = 0; mi < 4; ++mi) {
#pragma unroll
        for (int ni = 0; ni < 4; ++ni) {
            int r0 = m0 + wm * 64 + mi * 16 + (lane >> 2);
            int cc = n0 + wn * 32 + ni * 8 + ((lane & 3) << 1);
            if (MODE == 0) {
                *(__half2*)(g_xzh + (size_t)r0 * Nd + cc) =
                    __floats2half2_rn(c[mi][ni][0], c[mi][ni][1]);
                *(__half2*)(g_xzh + (size_t)(r0 + 8) * Nd + cc) =
                    __floats2half2_rn(c[mi][ni][2], c[mi][ni][3]);
            } else {
                float2 ra = *(const float2*)(resid + (size_t)r0 * Nd + cc);
                float2 rb = *(const float2*)(resid + (size_t)(r0 + 8) * Nd + cc);
                float2 oa = make_float2(c[mi][ni][0] + ra.x, c[mi][ni][1] + ra.y);
                float2 ob = make_float2(c[mi][ni][2] + rb.x, c[mi][ni][3] + rb.y);
                *(float2*)(Cout + (size_t)r0 * Nd + cc) = oa;
                *(float2*)(Cout + (size_t)(r0 + 8) * Nd + cc) = ob;
            }
        }
    }
}

// ---------------- depthwise 3x3 conv + bias + silu: sliding-window row kernel ----
// grid = (h, channel-half, b); 256 threads; thread handles 2 channels across w.
__global__ void __launch_bounds__(256) conv_kernel(const float* __restrict__ cw,
                                                   const float* __restrict__ cb) {
    int h = blockIdx.x, b = blockIdx.z;
    int d = blockIdx.y * 512 + threadIdx.x * 2;

    float wa[9], wb[9];
#pragma unroll
    for (int i = 0; i < 9; ++i) {
        wa[i] = __ldg(cw + d * 9 + i);
        wb[i] = __ldg(cw + (d + 1) * 9 + i);
    }
    float bias0 = __ldg(cb + d), bias1 = __ldg(cb + d + 1);

    const __half2* row[3];
    bool rv[3];
#pragma unroll
    for (int r = 0; r < 3; ++r) {
        int hh = h + r - 1;
        rv[r] = (unsigned)hh < 32u;
        row[r] = (const __half2*)(g_xzh + ((size_t)(b * L_ + ((hh & 31) << 5))) * (2 * DI_) + d);
    }

    float2 c0[3], c1[3], c2[3];
#pragma unroll
    for (int r = 0; r < 3; ++r) {
        c0[r] = make_float2(0.f, 0.f);
        c1[r] = rv[r] ? __half22float2(row[r][0])          : make_float2(0.f, 0.f);
        c2[r] = rv[r] ? __half22float2(row[r][(size_t)DI_]) : make_float2(0.f, 0.f);
    }

    __half2* outp = (__half2*)(g_xch + ((size_t)(b * L_ + (h << 5))) * DI_ + d);
#pragma unroll 4
    for (int w = 0; w < 32; ++w) {
        float a0 = bias0, a1 = bias1;
#pragma unroll
        for (int r = 0; r < 3; ++r) {
            a0 = fmaf(c0[r].x, wa[r * 3 + 0], a0);
            a0 = fmaf(c1[r].x, wa[r * 3 + 1], a0);
            a0 = fmaf(c2[r].x, wa[r * 3 + 2], a0);
            a1 = fmaf(c0[r].y, wb[r * 3 + 0], a1);
            a1 = fmaf(c1[r].y, wb[r * 3 + 1], a1);
            a1 = fmaf(c2[r].y, wb[r * 3 + 2], a1);
        }
        float s0 = a0 / (1.0f + __expf(-a0));
        float s1 = a1 / (1.0f + __expf(-a1));
        outp[(size_t)w * (DI_ / 2)] = __floats2half2_rn(s0, s1);

        int wn = w + 2;
        bool wv = wn < 32;
#pragma unroll
        for (int r = 0; r < 3; ++r) {
            c0[r] = c1[r];
            c1[r] = c2[r];
            c2[r] = (rv[r] && wv) ? __half22float2(row[r][(size_t)wn * DI_])
                                  : make_float2(0.f, 0.f);
        }
    }
}

// ---------------- x_dbl via tensor cores, cp.async double-buffered ----------------
// epilogue splits: cols 0:32 (dt ranks) -> half g_xdth; cols 32:64 (B/C) -> fp32 g_xbc
__global__ void __launch_bounds__(256) xdbl_kernel() {
    int k = blockIdx.y, b = blockIdx.z;
    int t0 = blockIdx.x * 128;
    int bk = b * K_ + k;

    __shared__ __half As[2][128][40];
    __shared__ __half Bs[2][64][40];

    int tid = threadIdx.x;
    int lane = tid & 31, wid = tid >> 5;
    int wm = wid & 3, wn = wid >> 2;

    const __half* xcb = g_xch + (size_t)b * L_ * DI_;
    const __half* Wh = g_wX + (size_t)k * 64 * DI_;

    float c[2][4][4];
#pragma unroll
    for (int i = 0; i < 2; ++i)
#pragma unroll
        for (int j = 0; j < 4; ++j)
#pragma unroll
            for (int e = 0; e < 4; ++e) c[i][j][e] = 0.0f;

    int lrow = tid >> 2;
    int lseg = (tid & 3) * 8;
    int lsp0 = map_t(k, t0 + lrow);
    int lsp1 = map_t(k, t0 + 64 + lrow);
    const __half* pa0 = xcb + (size_t)lsp0 * DI_ + lseg;
    const __half* pa1 = xcb + (size_t)lsp1 * DI_ + lseg;
    int brow = tid >> 2;
    int bseg = (tid & 3) * 8;
    const __half* pbb = Wh + (size_t)brow * DI_ + bseg;

    {
        cp16(smem_u32(&As[0][lrow][lseg]), pa0);
        cp16(smem_u32(&As[0][64 + lrow][lseg]), pa1);
        cp16(smem_u32(&Bs[0][brow][bseg]), pbb);
        CP_COMMIT();
    }

    for (int it = 0; it < DI_ / 32; ++it) {
        if (it + 1 < DI_ / 32) {
            int s = (it + 1) & 1;
            int dk = (it + 1) * 32;
            cp16(smem_u32(&As[s][lrow][lseg]), pa0 + dk);
            cp16(smem_u32(&As[s][64 + lrow][lseg]), pa1 + dk);
            cp16(smem_u32(&Bs[s][brow][bseg]), pbb + dk);
            CP_COMMIT();
            CP_WAIT1();
        } else {
            CP_WAIT0();
        }
        __syncthreads();
        int s = it & 1;
#pragma unroll
        for (int kk = 0; kk < 2; ++kk) {
            uint32_t a[2][4];
#pragma unroll
            for (int mi = 0; mi < 2; ++mi) {
                uint32_t addr = smem_u32(&As[s][wm * 32 + mi * 16 + (lane & 15)]
                                              [kk * 16 + ((lane >> 4) << 3)]);
                ldsm4(a[mi], addr);
            }
            uint32_t bfr[4][2];
#pragma unroll
            for (int nj = 0; nj < 2; ++nj) {
                int n_off = (lane & 7) + ((lane >> 4) << 3);
                int kh = ((lane >> 3) & 1) * 8;
                uint32_t addr = smem_u32(&Bs[s][wn * 32 + nj * 16 + n_off][kk * 16 + kh]);
                uint32_t t4[4];
                ldsm4(t4, addr);
                bfr[2 * nj][0] = t4[0]; bfr[2 * nj][1] = t4[1];
                bfr[2 * nj + 1][0] = t4[2]; bfr[2 * nj + 1][1] = t4[3];
            }
#pragma unroll
            for (int mi = 0; mi < 2; ++mi)
#pragma unroll
                for (int ni = 0; ni < 4; ++ni)
                    mma16816(c[mi][ni], a[mi], bfr[ni]);
        }
        __syncthreads();
    }

#pragma unroll
    for (int mi = 0; mi < 2; ++mi) {
#pragma unroll
        for (int ni = 0; ni < 4; ++ni) {
            int r0 = wm * 32 + mi * 16 + (lane >> 2);
            int cc = ni * 8 + ((lane & 3) << 1);   // 0..31 within the warp's half
            if (wn == 0) {
                __half* dst = g_xdth + ((size_t)bk * L_ + t0 + r0) * 32 + cc;
                *(__half2*)dst = __floats2half2_rn(c[mi][ni][0], c[mi][ni][1]);
                __half* dst2 = g_xdth + ((size_t)bk * L_ + t0 + r0 + 8) * 32 + cc;
                *(__half2*)dst2 = __floats2half2_rn(c[mi][ni][2], c[mi][ni][3]);
            } else {
                float* dst = g_xbc + ((size_t)bk * L_ + t0 + r0) * 32 + cc;
                *(float2*)dst = make_float2(c[mi][ni][0], c[mi][ni][1]);
                float* dst2 = g_xbc + ((size_t)bk * L_ + t0 + r0 + 8) * 32 + cc;
                *(float2*)dst2 = make_float2(c[mi][ni][2], c[mi][ni][3]);
            }
        }
    }
}

// ---------------- dts via tensor cores: [L x DI x 32] per bk + softplus ----------
__global__ void __launch_bounds__(256) dts_kernel(const float* __restrict__ dtb) {
    int bk = blockIdx.z;
    int k = bk & 3;
    int t0 = blockIdx.y * 128, d0 = blockIdx.x * 128;

    __shared__ __half As[128][40];
    __shared__ __half Bs[128][40];

    int tid = threadIdx.x;
    int lane = tid & 31, wid = tid >> 5;
    int wm = wid & 1, wn = wid >> 1;

#pragma unroll
    for (int it2 = 0; it2 < 2; ++it2) {
        int idx = tid + it2 * 256;
        int row = idx >> 2;
        int seg = (idx & 3) * 8;
        cp16(smem_u32(&As[row][seg]),
             g_xdth + ((size_t)bk * L_ + t0 + row) * 32 + seg);
        cp16(smem_u32(&Bs[row][seg]),
             g_wD + ((size_t)(k * DI_ + d0 + row)) * R_ + seg);
    }
    CP_COMMIT();
    CP_WAIT0();
    __syncthreads();

    float c[4][4][4];
#pragma unroll
    for (int i = 0; i < 4; ++i)
#pragma unroll
        for (int j = 0; j < 4; ++j)
#pragma unroll
            for (int e = 0; e < 4; ++e) c[i][j][e] = 0.0f;

#pragma unroll
    for (int kk = 0; kk < 2; ++kk) {
        uint32_t a[4][4];
#pragma unroll
        for (int mi = 0; mi < 4; ++mi) {
            uint32_t addr = smem_u32(&As[wm * 64 + mi * 16 + (lane & 15)]
                                       [kk * 16 + ((lane >> 4) << 3)]);
            ldsm4(a[mi], addr);
        }
        uint32_t bfr[4][2];
#pragma unroll
        for (int nj = 0; nj < 2; ++nj) {
            int n_off = (lane & 7) + ((lane >> 4) << 3);
            int kh = ((lane >> 3) & 1) * 8;
            uint32_t addr = smem_u32(&Bs[wn * 32 + nj * 16 + n_off][kk * 16 + kh]);
            uint32_t t4[4];
            ldsm4(t4, addr);
            bfr[2 * nj][0] = t4[0]; bfr[2 * nj][1] = t4[1];
            bfr[2 * nj + 1][0] = t4[2]; bfr[2 * nj + 1][1] = t4[3];
        }
#pragma unroll
        for (int mi = 0; mi < 4; ++mi)
#pragma unroll
            for (int ni = 0; ni < 4; ++ni)
                mma16816(c[mi][ni], a[mi], bfr[ni]);
    }

#pragma unroll
    for (int mi = 0; mi < 4; ++mi) {
#pragma unroll
        for (int ni = 0; ni < 4; ++ni) {
            int r0 = t0 + wm * 64 + mi * 16 + (lane >> 2);
            int cc = d0 + wn * 32 + ni * 8 + ((lane & 3) << 1);
            float b0 = __ldg(dtb + k * DI_ + cc);
            float b1 = __ldg(dtb + k * DI_ + cc + 1);
            float v0 = c[mi][ni][0] + b0, v1 = c[mi][ni][1] + b1;
            float v2 = c[mi][ni][2] + b0, v3 = c[mi][ni][3] + b1;
            float s0 = fmaxf(v0, 0.0f) + __logf(1.0f + __expf(-fabsf(v0)));
            float s1 = fmaxf(v1, 0.0f) + __logf(1.0f + __expf(-fabsf(v1)));
            float s2 = fmaxf(v2, 0.0f) + __logf(1.0f + __expf(-fabsf(v2)));
            float s3 = fmaxf(v3, 0.0f) + __logf(1.0f + __expf(-fabsf(v3)));
            *(__half2*)(g_dtsh + ((size_t)bk * L_ + r0) * DI_ + cc) =
                __floats2half2_rn(s0, s1);
            *(__half2*)(g_dtsh + ((size_t)bk * L_ + r0 + 8) * DI_ + cc) =
                __floats2half2_rn(s2, s3);
        }
    }
}

// ---------------- selective scan: packed f32x2 + integer-A fast path (R10 exact) ----
// thread = (b, k, d); 128 threads/block, 256 blocks (2 co-resident blocks/SM).
__global__ void __launch_bounds__(128) scan_kernel(const float* __restrict__ A_logs,
                                                   const float* __restrict__ Ds) {
    int b = blockIdx.z, k = blockIdx.y;
    int d = blockIdx.x * 128 + threadIdx.x;
    int bk = b * K_ + k;
    int row = k * DI_ + d;

    float An[N_];
#pragma unroll
    for (int n = 0; n < N_; ++n) An[n] = -__expf(A_logs[(size_t)row * N_ + n]);
    float A1 = An[0];
    bool fast = true;
#pragma unroll
    for (int n = 1; n < N_; ++n)
        fast = fast && (fabsf(An[n] - (float)(n + 1) * A1) <= 1e-4f * fabsf(An[n]));

    float Dv = Ds[row];
    u64t h2[8];
#pragma unroll
    for (int j = 0; j < 8; ++j) h2[j] = 0ull;

    const float* xd = g_xbc + (size_t)bk * L_ * 32;
    const __half* dtp = g_dtsh + (size_t)bk * L_ * DI_ + d;
    __half* ysk = g_ysh + (size_t)bk * L_ * DI_ + d;
    const __half* up = g_xch + (size_t)b * L_ * DI_ + d;

    __shared__ u64t sbc[64][16];   // [tt][pair]: pairs 0..7 = B, 8..15 = C

    float ubuf[2], dtbuf[2];
    ubuf[0]  = __half2float(__ldg(up + (size_t)map_t(k, 0) * DI_));
    dtbuf[0] = __half2float(__ldg(dtp));
    ubuf[1]  = __half2float(__ldg(up + (size_t)map_t(k, 1) * DI_));
    dtbuf[1] = __half2float(__ldg(dtp + DI_));

    for (int t0 = 0; t0 < L_; t0 += 64) {
        __syncthreads();
#pragma unroll
        for (int i = 0; i < 8; ++i) {
            int p = threadIdx.x + i * 128;       // 0..1023
            int tt = p >> 4, c2 = p & 15;
            float2 v = *(const float2*)(xd + (size_t)(t0 + tt) * 32 + 2 * c2);
            sbc[tt][c2] = pack2(v.x, v.y);
        }
        __syncthreads();

        if (fast) {
#pragma unroll 2
            for (int tt = 0; tt < 64; ++tt) {
                int t = t0 + tt;
                float u  = ubuf[t & 1];
                float dt = dtbuf[t & 1];
                int tn = t + 2;
                if (tn < L_) {
                    ubuf[t & 1]  = __half2float(__ldg(up + (size_t)map_t(k, tn) * DI_));
                    dtbuf[t & 1] = __half2float(__ldg(dtp + (size_t)tn * DI_));
                }
                float du = dt * u;
                u64t du2 = pack2(du, du);
                float e1 = __expf(dt * A1);
                float e2s = e1 * e1;
                u64t dAj = pack2(e1, e2s);
                u64t E2 = pack2(e2s, e2s);
                u64t yacc = pack2(Dv * u, 0.0f);
                const ulonglong2* pr = (const ulonglong2*)&sbc[tt][0];
                u64t bc[16];
#pragma unroll
                for (int jj = 0; jj < 8; ++jj) {
                    ulonglong2 q = pr[jj];
                    bc[2 * jj] = q.x; bc[2 * jj + 1] = q.y;
                }
#pragma unroll
                for (int j = 0; j < 8; ++j) {
                    u64t tmp = mul2(du2, bc[j]);
                    h2[j] = fma2(h2[j], dAj, tmp);
                    yacc = fma2(h2[j], bc[8 + j], yacc);
                    if (j < 7) dAj = mul2(dAj, E2);
                }
                float ylo, yhi;
                unpack2(ylo, yhi, yacc);
                ysk[(size_t)map_t(k, t) * DI_] = __float2half_rn(ylo + yhi);
            }
        } else {
#pragma unroll 2
            for (int tt = 0; tt < 64; ++tt) {
                int t = t0 + tt;
                float u  = ubuf[t & 1];
                float dt = dtbuf[t & 1];
                int tn = t + 2;
                if (tn < L_) {
                    ubuf[t & 1]  = __half2float(__ldg(up + (size_t)map_t(k, tn) * DI_));
                    dtbuf[t & 1] = __half2float(__ldg(dtp + (size_t)tn * DI_));
                }
                float du = dt * u;
                u64t du2 = pack2(du, du);
                u64t yacc = pack2(Dv * u, 0.0f);
                const ulonglong2* pr = (const ulonglong2*)&sbc[tt][0];
                u64t bc[16];
#pragma unroll
                for (int jj = 0; jj < 8; ++jj) {
                    ulonglong2 q = pr[jj];
                    bc[2 * jj] = q.x; bc[2 * jj + 1] = q.y;
                }
#pragma unroll
                for (int j = 0; j < 8; ++j) {
                    u64t dA2 = pack2(__expf(dt * An[2 * j]), __expf(dt * An[2 * j + 1]));
                    u64t tmp = mul2(du2, bc[j]);
                    h2[j] = fma2(h2[j], dA2, tmp);
                    yacc = fma2(h2[j], bc[8 + j], yacc);
                }
                float ylo, yhi;
                unpack2(ylo, yhi, yacc);
                ysk[(size_t)map_t(k, t) * DI_] = __float2half_rn(ylo + yhi);
            }
        }
    }
}

// ---------------- combine 4 dirs + out-layernorm + silu(z) gate -> half ----------------
__global__ void __launch_bounds__(256) combine_kernel(const float* __restrict__ onw,
                                                      const float* __restrict__ onb) {
    int bl = blockIdx.x;
    int b = bl >> 10;
    int l = bl & 1023;
    int tid = threadIdx.x;
    int d0 = tid * 4;

    float a0 = 0.f, a1 = 0.f, a2 = 0.f, a3 = 0.f;
#pragma unroll
    for (int k = 0; k < K_; ++k) {
        const __half* p = g_ysh + (((size_t)(b * K_ + k)) * L_ + l) * DI_ + d0;
        __half2 h01 = *(const __half2*)(p);
        __half2 h23 = *(const __half2*)(p + 2);
        float2 f01 = __half22float2(h01);
        float2 f23 = __half22float2(h23);
        a0 += f01.x; a1 += f01.y; a2 += f23.x; a3 += f23.y;
    }
    float s = a0 + a1 + a2 + a3;
    float q = a0 * a0 + a1 * a1 + a2 * a2 + a3 * a3;
#pragma unroll
    for (int o = 16; o; o >>= 1) {
        s += __shfl_xor_sync(0xffffffffu, s, o);
        q += __shfl_xor_sync(0xffffffffu, q, o);
    }
    __shared__ float shs[8], shq[8];
    if ((tid & 31) == 0) { shs[tid >> 5] = s; shq[tid >> 5] = q; }
    __syncthreads();
    float S = 0.f, Q = 0.f;
#pragma unroll
    for (int i = 0; i < 8; ++i) { S += shs[i]; Q += shq[i]; }
    float mu  = S * (1.0f / DI_);
    float var = Q * (1.0f / DI_) - mu * mu;
    float rs  = rsqrtf(var + 1e-5f);

    float4 wv = *(const float4*)(onw + d0);
    float4 bv = *(const float4*)(onb + d0);
    const __half* zp = g_xzh + (size_t)bl * (2 * DI_) + DI_ + d0;
    float2 z01 = __half22float2(*(const __half2*)(zp));
    float2 z23 = __half22float2(*(const __half2*)(zp + 2));

    float ln0 = (a0 - mu) * rs * wv.x + bv.x;
    float ln1 = (a1 - mu) * rs * wv.y + bv.y;
    float ln2 = (a2 - mu) * rs * wv.z + bv.z;
    float ln3 = (a3 - mu) * rs * wv.w + bv.w;
    float o0 = ln0 * (z01.x / (1.0f + __expf(-z01.x)));
    float o1 = ln1 * (z01.y / (1.0f + __expf(-z01.y)));
    float o2 = ln2 * (z23.x / (1.0f + __expf(-z23.x)));
    float o3 = ln3 * (z23.y / (1.0f + __expf(-z23.y)));

    __half* dst = g_yfh + (size_t)bl * DI_ + d0;
    *(__half2*)(dst)     = __floats2half2_rn(o0, o1);
    *(__half2*)(dst + 2) = __floats2half2_rn(o2, o3);
}

// ---------------- launch ----------------
extern "C" void kernel_launch(void* const* d_in, const int* in_sizes, int n_in,
                              void* d_out, int out_size) {
    const float* x          = (const float*)d_in[0];
    const float* norm_w     = (const float*)d_in[1];
    const float* norm_b     = (const float*)d_in[2];
    const float* in_proj_w  = (const float*)d_in[3];
    const float* conv_w     = (const float*)d_in[4];
    const float* conv_b     = (const float*)d_in[5];
    const float* x_proj_w   = (const float*)d_in[6];
    const float* dt_projs_w = (const float*)d_in[7];
    const float* dt_projs_b = (const float*)d_in[8];
    const float* A_logs     = (const float*)d_in[9];
    const float* Ds         = (const float*)d_in[10];
    const float* out_norm_w = (const float*)d_in[11];
    const float* out_norm_b = (const float*)d_in[12];
    const float* out_proj_w = (const float*)d_in[13];
    float* out = (float*)d_out;

    prep_kernel<<<4096 + ML_, 256>>>(in_proj_w, out_proj_w, x_proj_w, dt_projs_w,
                                     x, norm_w, norm_b);                     // 1
    hgemm_nt<0><<<dim3((2 * DI_) / 128, ML_ / 128), 256>>>(nullptr, nullptr); // 2
    conv_kernel<<<dim3(H_, 2, B_), 256>>>(conv_w, conv_b);                   // 3
    xdbl_kernel<<<dim3(L_ / 128, K_, B_), 256>>>();                          // 4 (profiled)
    dts_kernel<<<dim3(DI_ / 128, L_ / 128, B_ * K_), 256>>>(dt_projs_b);     // 5
    scan_kernel<<<dim3(DI_ / 128, K_, B_), 128>>>(A_logs, Ds);               // 6
    combine_kernel<<<ML_, 256>>>(out_norm_w, out_norm_b);                    // 7
    hgemm_nt<1><<<dim3(C_ / 128, ML_ / 128), 256>>>(x, out);                 // 8
}

// round 16
// speedup vs baseline: 1.5025x; 1.4683x over previous
#include <cuda_runtime.h>
#include <cuda_fp16.h>
#include <math.h>
#include <stdint.h>

// ---------------- problem constants ----------------
#define B_   8
#define H_   32
#define W_   32
#define L_   1024
#define C_   512
#define DI_  1024
#define K_   4
#define N_   16
#define R_   32
#define ML_  (B_ * L_)          // 8192 rows

// ---------------- scratch (device globals) ----------------
__device__ __half g_xnh [(size_t)ML_ * C_];            // layernorm(x)  (half)
__device__ __half g_xzh [(size_t)ML_ * 2 * DI_];       // in_proj out   (half)
__device__ __half g_xch [(size_t)ML_ * DI_];           // conv+silu     (half)
__device__ __half g_xdth[(size_t)B_ * K_ * L_ * 32];   // x_dbl dt-part (half)
__device__ float  g_xbc [(size_t)B_ * K_ * L_ * 32];   // x_dbl B/C     fp32
__device__ __half g_dtsh[(size_t)B_ * K_ * L_ * DI_];  // (bk, t, d)    half
__device__ __half g_ysh [(size_t)B_ * K_ * L_ * DI_];  // (bk, l, d)    half
__device__ __half g_yfh [(size_t)ML_ * DI_];           // pre-out_proj  half
__device__ __half g_wA  [2 * DI_ * C_];                // in_proj_w  half
__device__ __half g_wB  [C_ * DI_];                    // out_proj_w half
__device__ __half g_wX  [K_ * 64 * DI_];               // x_proj_w   half
__device__ __half g_wD  [K_ * DI_ * R_];               // dt_projs_w half

// scan index map: spatial l for direction k at scan step t
__device__ __forceinline__ int map_t(int k, int t) {
    int tt = (k & 2) ? (L_ - 1 - t) : t;
    return (k & 1) ? (((tt & 31) << 5) | (tt >> 5)) : tt;
}

__device__ __forceinline__ uint32_t smem_u32(const void* p) {
    return (uint32_t)__cvta_generic_to_shared(p);
}
__device__ __forceinline__ void ldsm4(uint32_t* r, uint32_t addr) {
    asm volatile("ldmatrix.sync.aligned.m8n8.x4.shared.b16 {%0,%1,%2,%3}, [%4];"
                 : "=r"(r[0]), "=r"(r[1]), "=r"(r[2]), "=r"(r[3]) : "r"(addr));
}
__device__ __forceinline__ void mma16816(float* c, const uint32_t* a, const uint32_t* b) {
    asm volatile("mma.sync.aligned.m16n8k16.row.col.f32.f16.f16.f32 "
                 "{%0,%1,%2,%3}, {%4,%5,%6,%7}, {%8,%9}, {%0,%1,%2,%3};"
                 : "+f"(c[0]), "+f"(c[1]), "+f"(c[2]), "+f"(c[3])
                 : "r"(a[0]), "r"(a[1]), "r"(a[2]), "r"(a[3]), "r"(b[0]), "r"(b[1]));
}
__device__ __forceinline__ void cp16(uint32_t dst, const void* src) {
    asm volatile("cp.async.cg.shared.global [%0], [%1], 16;\n" :: "r"(dst), "l"(src));
}
#define CP_COMMIT() asm volatile("cp.async.commit_group;\n" ::: "memory")
#define CP_WAIT1()  asm volatile("cp.async.wait_group 1;\n" ::: "memory")
#define CP_WAIT0()  asm volatile("cp.async.wait_group 0;\n" ::: "memory")

// ---------------- packed f32x2 helpers (sm_100+) ----------------
typedef unsigned long long u64t;
__device__ __forceinline__ u64t pack2(float lo, float hi) {
    u64t r; asm("mov.b64 %0, {%1, %2};" : "=l"(r) : "f"(lo), "f"(hi)); return r;
}
__device__ __forceinline__ void unpack2(float& lo, float& hi, u64t v) {
    asm("mov.b64 {%0, %1}, %2;" : "=f"(lo), "=f"(hi) : "l"(v));
}
__device__ __forceinline__ u64t mul2(u64t a, u64t b) {
    u64t r; asm("mul.rn.f32x2 %0, %1, %2;" : "=l"(r) : "l"(a), "l"(b)); return r;
}
__device__ __forceinline__ u64t fma2(u64t a, u64t b, u64t c) {
    u64t r; asm("fma.rn.f32x2 %0, %1, %2, %3;" : "=l"(r) : "l"(a), "l"(b), "l"(c)); return r;
}

// ---------------- prep: weight fp32->fp16 convert + input layernorm, fused --------
__global__ void __launch_bounds__(256) prep_kernel(const float* __restrict__ ipw,
                                                   const float* __restrict__ opw,
                                                   const float* __restrict__ xpw,
                                                   const float* __restrict__ dtw,
                                                   const float* __restrict__ x,
                                                   const float* __restrict__ nw,
                                                   const float* __restrict__ nb) {
    int bid = blockIdx.x;
    int tid = threadIdx.x;
    if (bid < 4096) {
        int i = bid * 256 + tid;
        g_wA[i] = __float2half_rn(ipw[i]);
        if (i < C_ * DI_)      g_wB[i] = __float2half_rn(opw[i]);
        if (i < K_ * 64 * DI_) g_wX[i] = __float2half_rn(xpw[i]);
        if (i < K_ * DI_ * R_) g_wD[i] = __float2half_rn(dtw[i]);
        return;
    }
    int bl = bid - 4096;
    const float* xr = x + (size_t)bl * C_;
    float2 v = *(const float2*)(xr + tid * 2);
    float s = v.x + v.y;
    float q = v.x * v.x + v.y * v.y;
#pragma unroll
    for (int o = 16; o; o >>= 1) {
        s += __shfl_xor_sync(0xffffffffu, s, o);
        q += __shfl_xor_sync(0xffffffffu, q, o);
    }
    __shared__ float shs[8], shq[8];
    if ((tid & 31) == 0) { shs[tid >> 5] = s; shq[tid >> 5] = q; }
    __syncthreads();
    float S = 0.f, Q = 0.f;
#pragma unroll
    for (int i = 0; i < 8; ++i) { S += shs[i]; Q += shq[i]; }
    float mu  = S * (1.0f / C_);
    float var = Q * (1.0f / C_) - mu * mu;
    float rs  = rsqrtf(var + 1e-5f);
    float2 wv = *(const float2*)(nw + tid * 2);
    float2 bv = *(const float2*)(nb + tid * 2);
    float o0 = (v.x - mu) * rs * wv.x + bv.x;
    float o1 = (v.y - mu) * rs * wv.y + bv.y;
    *(__half2*)(g_xnh + (size_t)bl * C_ + tid * 2) = __floats2half2_rn(o0, o1);
}

// ---------------- tensor-core NT hgemm, cp.async double-buffered (2-stage, R12) ----
template <int MODE>
__global__ void __launch_bounds__(256) hgemm_nt(const float* __restrict__ resid,
                                                float* __restrict__ Cout) {
    constexpr int Kd = (MODE == 0) ? C_ : DI_;
    constexpr int Nd = (MODE == 0) ? 2 * DI_ : C_;
    constexpr int NIT = Kd / 32;
    const __half* A = (MODE == 0) ? g_xnh : g_yfh;
    const __half* Wh = (MODE == 0) ? g_wA : g_wB;

    __shared__ __half As[2][128][40];
    __shared__ __half Bs[2][128][40];

    int tid = threadIdx.x;
    int lane = tid & 31, wid = tid >> 5;
    int wm = wid & 1, wn = wid >> 1;
    int m0 = blockIdx.y * 128, n0 = blockIdx.x * 128;

    float c[4][4][4];
#pragma unroll
    for (int i = 0; i < 4; ++i)
#pragma unroll
        for (int j = 0; j < 4; ++j)
#pragma unroll
            for (int e = 0; e < 4; ++e) c[i][j][e] = 0.0f;

    int lrow = tid >> 2;
    int lseg = (tid & 3) * 8;
    const __half* pa0 = A + (size_t)(m0 + lrow) * Kd + lseg;
    const __half* pa1 = A + (size_t)(m0 + 64 + lrow) * Kd + lseg;
    const __half* pb0 = Wh + (size_t)(n0 + lrow) * Kd + lseg;
    const __half* pb1 = Wh + (size_t)(n0 + 64 + lrow) * Kd + lseg;

    {
        cp16(smem_u32(&As[0][lrow][lseg]), pa0);
        cp16(smem_u32(&As[0][64 + lrow][lseg]), pa1);
        cp16(smem_u32(&Bs[0][lrow][lseg]), pb0);
        cp16(smem_u32(&Bs[0][64 + lrow][lseg]), pb1);
        CP_COMMIT();
    }

    for (int it = 0; it < NIT; ++it) {
        if (it + 1 < NIT) {
            int s = (it + 1) & 1;
            int k0 = (it + 1) * 32;
            cp16(smem_u32(&As[s][lrow][lseg]), pa0 + k0);
            cp16(smem_u32(&As[s][64 + lrow][lseg]), pa1 + k0);
            cp16(smem_u32(&Bs[s][lrow][lseg]), pb0 + k0);
            cp16(smem_u32(&Bs[s][64 + lrow][lseg]), pb1 + k0);
            CP_COMMIT();
            CP_WAIT1();
        } else {
            CP_WAIT0();
        }
        __syncthreads();
        int s = it & 1;
#pragma unroll
        for (int kk = 0; kk < 2; ++kk) {
            uint32_t a[4][4];
#pragma unroll
            for (int mi = 0; mi < 4; ++mi) {
                uint32_t addr = smem_u32(&As[s][wm * 64 + mi * 16 + (lane & 15)]
                                              [kk * 16 + ((lane >> 4) << 3)]);
                ldsm4(a[mi], addr);
            }
            uint32_t bfr[4][2];
#pragma unroll
            for (int nj = 0; nj < 2; ++nj) {
                int n_off = (lane & 7) + ((lane >> 4) << 3);
                int kh = ((lane >> 3) & 1) * 8;
                uint32_t addr = smem_u32(&Bs[s][wn * 32 + nj * 16 + n_off][kk * 16 + kh]);
                uint32_t t4[4];
                ldsm4(t4, addr);
                bfr[2 * nj][0] = t4[0]; bfr[2 * nj][1] = t4[1];
                bfr[2 * nj + 1][0] = t4[2]; bfr[2 * nj + 1][1] = t4[3];
            }
#pragma unroll
            for (int mi = 0; mi < 4; ++mi)
#pragma unroll
                for (int ni = 0; ni < 4; ++ni)
                    mma16816(c[mi][ni], a[mi], bfr[ni]);
        }
        __syncthreads();
    }

#pragma unroll
    for (int mi = 0; mi < 4; ++mi) {
#pragma unroll
        for (int ni = 0; ni < 4; ++ni) {
            int r0 = m0 + wm * 64 + mi * 16 + (lane >> 2);
            int cc = n0 + wn * 32 + ni * 8 + ((lane & 3) << 1);
            if (MODE == 0) {
                *(__half2*)(g_xzh + (size_t)r0 * Nd + cc) =
                    __floats2half2_rn(c[mi][ni][0], c[mi][ni][1]);
                *(__half2*)(g_xzh + (size_t)(r0 + 8) * Nd + cc) =
                    __floats2half2_rn(c[mi][ni][2], c[mi][ni][3]);
            } else {
                float2 ra = *(const float2*)(resid + (size_t)r0 * Nd + cc);
                float2 rb = *(const float2*)(resid + (size_t)(r0 + 8) * Nd + cc);
                float2 oa = make_float2(c[mi][ni][0] + ra.x, c[mi][ni][1] + ra.y);
                float2 ob = make_float2(c[mi][ni][2] + rb.x, c[mi][ni][3] + rb.y);
                *(float2*)(Cout + (size_t)r0 * Nd + cc) = oa;
                *(float2*)(Cout + (size_t)(r0 + 8) * Nd + cc) = ob;
            }
        }
    }
}

// ---------------- depthwise 3x3 conv + bias + silu: sliding-window row kernel ----
__global__ void __launch_bounds__(256) conv_kernel(const float* __restrict__ cw,
                                                   const float* __restrict__ cb) {
    int h = blockIdx.x, b = blockIdx.z;
    int d = blockIdx.y * 512 + threadIdx.x * 2;

    float wa[9], wb[9];
#pragma unroll
    for (int i = 0; i < 9; ++i) {
        wa[i] = __ldg(cw + d * 9 + i);
        wb[i] = __ldg(cw + (d + 1) * 9 + i);
    }
    float bias0 = __ldg(cb + d), bias1 = __ldg(cb + d + 1);

    const __half2* row[3];
    bool rv[3];
#pragma unroll
    for (int r = 0; r < 3; ++r) {
        int hh = h + r - 1;
        rv[r] = (unsigned)hh < 32u;
        row[r] = (const __half2*)(g_xzh + ((size_t)(b * L_ + ((hh & 31) << 5))) * (2 * DI_) + d);
    }

    float2 c0[3], c1[3], c2[3];
#pragma unroll
    for (int r = 0; r < 3; ++r) {
        c0[r] = make_float2(0.f, 0.f);
        c1[r] = rv[r] ? __half22float2(row[r][0])          : make_float2(0.f, 0.f);
        c2[r] = rv[r] ? __half22float2(row[r][(size_t)DI_]) : make_float2(0.f, 0.f);
    }

    __half2* outp = (__half2*)(g_xch + ((size_t)(b * L_ + (h << 5))) * DI_ + d);
#pragma unroll 4
    for (int w = 0; w < 32; ++w) {
        float a0 = bias0, a1 = bias1;
#pragma unroll
        for (int r = 0; r < 3; ++r) {
            a0 = fmaf(c0[r].x, wa[r * 3 + 0], a0);
            a0 = fmaf(c1[r].x, wa[r * 3 + 1], a0);
            a0 = fmaf(c2[r].x, wa[r * 3 + 2], a0);
            a1 = fmaf(c0[r].y, wb[r * 3 + 0], a1);
            a1 = fmaf(c1[r].y, wb[r * 3 + 1], a1);
            a1 = fmaf(c2[r].y, wb[r * 3 + 2], a1);
        }
        float s0 = a0 / (1.0f + __expf(-a0));
        float s1 = a1 / (1.0f + __expf(-a1));
        outp[(size_t)w * (DI_ / 2)] = __floats2half2_rn(s0, s1);

        int wn = w + 2;
        bool wv = wn < 32;
#pragma unroll
        for (int r = 0; r < 3; ++r) {
            c0[r] = c1[r];
            c1[r] = c2[r];
            c2[r] = (rv[r] && wv) ? __half22float2(row[r][(size_t)wn * DI_])
                                  : make_float2(0.f, 0.f);
        }
    }
}

// ---------------- x_dbl via tensor cores, cp.async double-buffered ----------------
__global__ void __launch_bounds__(256) xdbl_kernel() {
    int k = blockIdx.y, b = blockIdx.z;
    int t0 = blockIdx.x * 128;
    int bk = b * K_ + k;

    __shared__ __half As[2][128][40];
    __shared__ __half Bs[2][64][40];

    int tid = threadIdx.x;
    int lane = tid & 31, wid = tid >> 5;
    int wm = wid & 3, wn = wid >> 2;

    const __half* xcb = g_xch + (size_t)b * L_ * DI_;
    const __half* Wh = g_wX + (size_t)k * 64 * DI_;

    float c[2][4][4];
#pragma unroll
    for (int i = 0; i < 2; ++i)
#pragma unroll
        for (int j = 0; j < 4; ++j)
#pragma unroll
            for (int e = 0; e < 4; ++e) c[i][j][e] = 0.0f;

    int lrow = tid >> 2;
    int lseg = (tid & 3) * 8;
    int lsp0 = map_t(k, t0 + lrow);
    int lsp1 = map_t(k, t0 + 64 + lrow);
    const __half* pa0 = xcb + (size_t)lsp0 * DI_ + lseg;
    const __half* pa1 = xcb + (size_t)lsp1 * DI_ + lseg;
    int brow = tid >> 2;
    int bseg = (tid & 3) * 8;
    const __half* pbb = Wh + (size_t)brow * DI_ + bseg;

    {
        cp16(smem_u32(&As[0][lrow][lseg]), pa0);
        cp16(smem_u32(&As[0][64 + lrow][lseg]), pa1);
        cp16(smem_u32(&Bs[0][brow][bseg]), pbb);
        CP_COMMIT();
    }

    for (int it = 0; it < DI_ / 32; ++it) {
        if (it + 1 < DI_ / 32) {
            int s = (it + 1) & 1;
            int dk = (it + 1) * 32;
            cp16(smem_u32(&As[s][lrow][lseg]), pa0 + dk);
            cp16(smem_u32(&As[s][64 + lrow][lseg]), pa1 + dk);
            cp16(smem_u32(&Bs[s][brow][bseg]), pbb + dk);
            CP_COMMIT();
            CP_WAIT1();
        } else {
            CP_WAIT0();
        }
        __syncthreads();
        int s = it & 1;
#pragma unroll
        for (int kk = 0; kk < 2; ++kk) {
            uint32_t a[2][4];
#pragma unroll
            for (int mi = 0; mi < 2; ++mi) {
                uint32_t addr = smem_u32(&As[s][wm * 32 + mi * 16 + (lane & 15)]
                                              [kk * 16 + ((lane >> 4) << 3)]);
                ldsm4(a[mi], addr);
            }
            uint32_t bfr[4][2];
#pragma unroll
            for (int nj = 0; nj < 2; ++nj) {
                int n_off = (lane & 7) + ((lane >> 4) << 3);
                int kh = ((lane >> 3) & 1) * 8;
                uint32_t addr = smem_u32(&Bs[s][wn * 32 + nj * 16 + n_off][kk * 16 + kh]);
                uint32_t t4[4];
                ldsm4(t4, addr);
                bfr[2 * nj][0] = t4[0]; bfr[2 * nj][1] = t4[1];
                bfr[2 * nj + 1][0] = t4[2]; bfr[2 * nj + 1][1] = t4[3];
            }
#pragma unroll
            for (int mi = 0; mi < 2; ++mi)
#pragma unroll
                for (int ni = 0; ni < 4; ++ni)
                    mma16816(c[mi][ni], a[mi], bfr[ni]);
        }
        __syncthreads();
    }

#pragma unroll
    for (int mi = 0; mi < 2; ++mi) {
#pragma unroll
        for (int ni = 0; ni < 4; ++ni) {
            int r0 = wm * 32 + mi * 16 + (lane >> 2);
            int cc = ni * 8 + ((lane & 3) << 1);   // 0..31 within the warp's half
            if (wn == 0) {
                __half* dst = g_xdth + ((size_t)bk * L_ + t0 + r0) * 32 + cc;
                *(__half2*)dst = __floats2half2_rn(c[mi][ni][0], c[mi][ni][1]);
                __half* dst2 = g_xdth + ((size_t)bk * L_ + t0 + r0 + 8) * 32 + cc;
                *(__half2*)dst2 = __floats2half2_rn(c[mi][ni][2], c[mi][ni][3]);
            } else {
                float* dst = g_xbc + ((size_t)bk * L_ + t0 + r0) * 32 + cc;
                *(float2*)dst = make_float2(c[mi][ni][0], c[mi][ni][1]);
                float* dst2 = g_xbc + ((size_t)bk * L_ + t0 + r0 + 8) * 32 + cc;
                *(float2*)dst2 = make_float2(c[mi][ni][2], c[mi][ni][3]);
            }
        }
    }
}

// ---------------- dts via tensor cores: [L x DI x 32] per bk + softplus ----------
__global__ void __launch_bounds__(256) dts_kernel(const float* __restrict__ dtb) {
    int bk = blockIdx.z;
    int k = bk & 3;
    int t0 = blockIdx.y * 128, d0 = blockIdx.x * 128;

    __shared__ __half As[128][40];
    __shared__ __half Bs[128][40];

    int tid = threadIdx.x;
    int lane = tid & 31, wid = tid >> 5;
    int wm = wid & 1, wn = wid >> 1;

#pragma unroll
    for (int it2 = 0; it2 < 2; ++it2) {
        int idx = tid + it2 * 256;
        int row = idx >> 2;
        int seg = (idx & 3) * 8;
        cp16(smem_u32(&As[row][seg]),
             g_xdth + ((size_t)bk * L_ + t0 + row) * 32 + seg);
        cp16(smem_u32(&Bs[row][seg]),
             g_wD + ((size_t)(k * DI_ + d0 + row)) * R_ + seg);
    }
    CP_COMMIT();
    CP_WAIT0();
    __syncthreads();

    float c[4][4][4];
#pragma unroll
    for (int i = 0; i < 4; ++i)
#pragma unroll
        for (int j = 0; j < 4; ++j)
#pragma unroll
            for (int e = 0; e < 4; ++e) c[i][j][e] = 0.0f;

#pragma unroll
    for (int kk = 0; kk < 2; ++kk) {
        uint32_t a[4][4];
#pragma unroll
        for (int mi = 0; mi < 4; ++mi) {
            uint32_t addr = smem_u32(&As[wm * 64 + mi * 16 + (lane & 15)]
                                       [kk * 16 + ((lane >> 4) << 3)]);
            ldsm4(a[mi], addr);
        }
        uint32_t bfr[4][2];
#pragma unroll
        for (int nj = 0; nj < 2; ++nj) {
            int n_off = (lane & 7) + ((lane >> 4) << 3);
            int kh = ((lane >> 3) & 1) * 8;
            uint32_t addr = smem_u32(&Bs[wn * 32 + nj * 16 + n_off][kk * 16 + kh]);
            uint32_t t4[4];
            ldsm4(t4, addr);
            bfr[2 * nj][0] = t4[0]; bfr[2 * nj][1] = t4[1];
            bfr[2 * nj + 1][0] = t4[2]; bfr[2 * nj + 1][1] = t4[3];
        }
#pragma unroll
        for (int mi = 0; mi < 4; ++mi)
#pragma unroll
            for (int ni = 0; ni < 4; ++ni)
                mma16816(c[mi][ni], a[mi], bfr[ni]);
    }

#pragma unroll
    for (int mi = 0; mi < 4; ++mi) {
#pragma unroll
        for (int ni = 0; ni < 4; ++ni) {
            int r0 = t0 + wm * 64 + mi * 16 + (lane >> 2);
            int cc = d0 + wn * 32 + ni * 8 + ((lane & 3) << 1);
            float b0 = __ldg(dtb + k * DI_ + cc);
            float b1 = __ldg(dtb + k * DI_ + cc + 1);
            float v0 = c[mi][ni][0] + b0, v1 = c[mi][ni][1] + b1;
            float v2 = c[mi][ni][2] + b0, v3 = c[mi][ni][3] + b1;
            float s0 = fmaxf(v0, 0.0f) + __logf(1.0f + __expf(-fabsf(v0)));
            float s1 = fmaxf(v1, 0.0f) + __logf(1.0f + __expf(-fabsf(v1)));
            float s2 = fmaxf(v2, 0.0f) + __logf(1.0f + __expf(-fabsf(v2)));
            float s3 = fmaxf(v3, 0.0f) + __logf(1.0f + __expf(-fabsf(v3)));
            *(__half2*)(g_dtsh + ((size_t)bk * L_ + r0) * DI_ + cc) =
                __floats2half2_rn(s0, s1);
            *(__half2*)(g_dtsh + ((size_t)bk * L_ + r0 + 8) * DI_ + cc) =
                __floats2half2_rn(s2, s3);
        }
    }
}

// ---------------- selective scan: fully smem-staged tiles (bc + u + dt) ------------
// thread = (b, k, d); 128 threads/block, 256 blocks; dynamic smem 2 x 40 KB.
#define SCAN_STAGE_BYTES 40960
__global__ void __launch_bounds__(128) scan_kernel(const float* __restrict__ A_logs,
                                                   const float* __restrict__ Ds) {
    int b = blockIdx.z, k = blockIdx.y;
    int tid = threadIdx.x;
    int d = blockIdx.x * 128 + tid;
    int bk = b * K_ + k;
    int row = k * DI_ + d;

    extern __shared__ char sraw[];

    float An[N_];
#pragma unroll
    for (int n = 0; n < N_; ++n) An[n] = -__expf(A_logs[(size_t)row * N_ + n]);
    float A1 = An[0];
    bool fast = true;
#pragma unroll
    for (int n = 1; n < N_; ++n)
        fast = fast && (fabsf(An[n] - (float)(n + 1) * A1) <= 1e-4f * fabsf(An[n]));

    float Dv = Ds[row];
    u64t h2[8];
#pragma unroll
    for (int j = 0; j < 8; ++j) h2[j] = 0ull;

    const float* xd = g_xbc + (size_t)bk * L_ * 32;
    const __half* dtp = g_dtsh + (size_t)bk * L_ * DI_ + blockIdx.x * 128;
    const __half* up  = g_xch + (size_t)b * L_ * DI_ + blockIdx.x * 128;
    __half* ysk = g_ysh + (size_t)bk * L_ * DI_ + d;

    auto stage_load = [&](int ti) {
        int s = ti & 1;
        char* base = sraw + s * SCAN_STAGE_BYTES;
        uint32_t bc_s = smem_u32(base);
        uint32_t u_s  = smem_u32(base + 8192);
        uint32_t dt_s = smem_u32(base + 8192 + 16384);
        int t0 = ti * 64;
        // bc tile: 8192 contiguous bytes
        const char* bsrc = (const char*)(xd + (size_t)t0 * 32);
#pragma unroll
        for (int i = 0; i < 4; ++i) {
            int off = (tid + i * 128) * 16;
            cp16(bc_s + off, bsrc + off);
        }
        // u (gathered rows) and dt (strided rows): 64 rows x 256 B each
#pragma unroll
        for (int i = 0; i < 8; ++i) {
            int idx = tid + i * 128;        // 0..1023
            int rowi = idx >> 4;            // 0..63
            int segb = (idx & 15) * 16;     // 0..240
            int lsp = map_t(k, t0 + rowi);
            cp16(u_s + rowi * 256 + segb, (const char*)(up + (size_t)lsp * DI_) + segb);
            cp16(dt_s + rowi * 256 + segb, (const char*)(dtp + (size_t)(t0 + rowi) * DI_) + segb);
        }
    };

    stage_load(0);
    CP_COMMIT();

    for (int ti = 0; ti < L_ / 64; ++ti) {
        __syncthreads();                         // all warps done with tile ti-1 buffers
        if (ti + 1 < L_ / 64) stage_load(ti + 1);
        CP_COMMIT();
        CP_WAIT1();                              // tile ti data arrived
        __syncthreads();

        char* base = sraw + (ti & 1) * SCAN_STAGE_BYTES;
        const u64t* sbc = (const u64t*)base;                 // [64][16]
        const __half* su = (const __half*)(base + 8192);     // [64][128]
        const __half* sdt = (const __half*)(base + 24576);   // [64][128]

        if (fast) {
#pragma unroll 2
            for (int tt = 0; tt < 64; ++tt) {
                int t = ti * 64 + tt;
                float u  = __half2float(su[tt * 128 + tid]);
                float dt = __half2float(sdt[tt * 128 + tid]);
                float du = dt * u;
                u64t du2 = pack2(du, du);
                float e1 = __expf(dt * A1);
                float e2s = e1 * e1;
                u64t dAj = pack2(e1, e2s);
                u64t E2 = pack2(e2s, e2s);
                u64t yacc = pack2(Dv * u, 0.0f);
                const ulonglong2* pr = (const ulonglong2*)(sbc + tt * 16);
                u64t bc[16];
#pragma unroll
                for (int jj = 0; jj < 8; ++jj) {
                    ulonglong2 q = pr[jj];
                    bc[2 * jj] = q.x; bc[2 * jj + 1] = q.y;
                }
#pragma unroll
                for (int j = 0; j < 8; ++j) {
                    u64t tmp = mul2(du2, bc[j]);
                    h2[j] = fma2(h2[j], dAj, tmp);
                    yacc = fma2(h2[j], bc[8 + j], yacc);
                    if (j < 7) dAj = mul2(dAj, E2);
                }
                float ylo, yhi;
                unpack2(ylo, yhi, yacc);
                ysk[(size_t)map_t(k, t) * DI_] = __float2half_rn(ylo + yhi);
            }
        } else {
#pragma unroll 2
            for (int tt = 0; tt < 64; ++tt) {
                int t = ti * 64 + tt;
                float u  = __half2float(su[tt * 128 + tid]);
                float dt = __half2float(sdt[tt * 128 + tid]);
                float du = dt * u;
                u64t du2 = pack2(du, du);
                u64t yacc = pack2(Dv * u, 0.0f);
                const ulonglong2* pr = (const ulonglong2*)(sbc + tt * 16);
                u64t bc[16];
#pragma unroll
                for (int jj = 0; jj < 8; ++jj) {
                    ulonglong2 q = pr[jj];
                    bc[2 * jj] = q.x; bc[2 * jj + 1] = q.y;
                }
#pragma unroll
                for (int j = 0; j < 8; ++j) {
                    u64t dA2 = pack2(__expf(dt * An[2 * j]), __expf(dt * An[2 * j + 1]));
                    u64t tmp = mul2(du2, bc[j]);
                    h2[j] = fma2(h2[j], dA2, tmp);
                    yacc = fma2(h2[j], bc[8 + j], yacc);
                }
                float ylo, yhi;
                unpack2(ylo, yhi, yacc);
                ysk[(size_t)map_t(k, t) * DI_] = __float2half_rn(ylo + yhi);
            }
        }
    }
}

// ---------------- combine 4 dirs + out-layernorm + silu(z) gate -> half ----------------
__global__ void __launch_bounds__(256) combine_kernel(const float* __restrict__ onw,
                                                      const float* __restrict__ onb) {
    int bl = blockIdx.x;
    int b = bl >> 10;
    int l = bl & 1023;
    int tid = threadIdx.x;
    int d0 = tid * 4;

    float a0 = 0.f, a1 = 0.f, a2 = 0.f, a3 = 0.f;
#pragma unroll
    for (int k = 0; k < K_; ++k) {
        const __half* p = g_ysh + (((size_t)(b * K_ + k)) * L_ + l) * DI_ + d0;
        __half2 h01 = *(const __half2*)(p);
        __half2 h23 = *(const __half2*)(p + 2);
        float2 f01 = __half22float2(h01);
        float2 f23 = __half22float2(h23);
        a0 += f01.x; a1 += f01.y; a2 += f23.x; a3 += f23.y;
    }
    float s = a0 + a1 + a2 + a3;
    float q = a0 * a0 + a1 * a1 + a2 * a2 + a3 * a3;
#pragma unroll
    for (int o = 16; o; o >>= 1) {
        s += __shfl_xor_sync(0xffffffffu, s, o);
        q += __shfl_xor_sync(0xffffffffu, q, o);
    }
    __shared__ float shs[8], shq[8];
    if ((tid & 31) == 0) { shs[tid >> 5] = s; shq[tid >> 5] = q; }
    __syncthreads();
    float S = 0.f, Q = 0.f;
#pragma unroll
    for (int i = 0; i < 8; ++i) { S += shs[i]; Q += shq[i]; }
    float mu  = S * (1.0f / DI_);
    float var = Q * (1.0f / DI_) - mu * mu;
    float rs  = rsqrtf(var + 1e-5f);

    float4 wv = *(const float4*)(onw + d0);
    float4 bv = *(const float4*)(onb + d0);
    const __half* zp = g_xzh + (size_t)bl * (2 * DI_) + DI_ + d0;
    float2 z01 = __half22float2(*(const __half2*)(zp));
    float2 z23 = __half22float2(*(const __half2*)(zp + 2));

    float ln0 = (a0 - mu) * rs * wv.x + bv.x;
    float ln1 = (a1 - mu) * rs * wv.y + bv.y;
    float ln2 = (a2 - mu) * rs * wv.z + bv.z;
    float ln3 = (a3 - mu) * rs * wv.w + bv.w;
    float o0 = ln0 * (z01.x / (1.0f + __expf(-z01.x)));
    float o1 = ln1 * (z01.y / (1.0f + __expf(-z01.y)));
    float o2 = ln2 * (z23.x / (1.0f + __expf(-z23.x)));
    float o3 = ln3 * (z23.y / (1.0f + __expf(-z23.y)));

    __half* dst = g_yfh + (size_t)bl * DI_ + d0;
    *(__half2*)(dst)     = __floats2half2_rn(o0, o1);
    *(__half2*)(dst + 2) = __floats2half2_rn(o2, o3);
}

// ---------------- launch ----------------
extern "C" void kernel_launch(void* const* d_in, const int* in_sizes, int n_in,
                              void* d_out, int out_size) {
    const float* x          = (const float*)d_in[0];
    const float* norm_w     = (const float*)d_in[1];
    const float* norm_b     = (const float*)d_in[2];
    const float* in_proj_w  = (const float*)d_in[3];
    const float* conv_w     = (const float*)d_in[4];
    const float* conv_b     = (const float*)d_in[5];
    const float* x_proj_w   = (const float*)d_in[6];
    const float* dt_projs_w = (const float*)d_in[7];
    const float* dt_projs_b = (const float*)d_in[8];
    const float* A_logs     = (const float*)d_in[9];
    const float* Ds         = (const float*)d_in[10];
    const float* out_norm_w = (const float*)d_in[11];
    const float* out_norm_b = (const float*)d_in[12];
    const float* out_proj_w = (const float*)d_in[13];
    float* out = (float*)d_out;

    constexpr int SCAN_SMEM = 2 * SCAN_STAGE_BYTES;   // 81920 B
    static bool attr_set = false;
    if (!attr_set) {
        cudaFuncSetAttribute(scan_kernel, cudaFuncAttributeMaxDynamicSharedMemorySize, SCAN_SMEM);
        attr_set = true;
    }

    prep_kernel<<<4096 + ML_, 256>>>(in_proj_w, out_proj_w, x_proj_w, dt_projs_w,
                                     x, norm_w, norm_b);                      // 1
    hgemm_nt<0><<<dim3((2 * DI_) / 128, ML_ / 128), 256>>>(nullptr, nullptr); // 2
    conv_kernel<<<dim3(H_, 2, B_), 256>>>(conv_w, conv_b);                    // 3
    xdbl_kernel<<<dim3(L_ / 128, K_, B_), 256>>>();                           // 4 (profiled)
    dts_kernel<<<dim3(DI_ / 128, L_ / 128, B_ * K_), 256>>>(dt_projs_b);      // 5
    scan_kernel<<<dim3(DI_ / 128, K_, B_), 128, SCAN_SMEM>>>(A_logs, Ds);     // 6
    combine_kernel<<<ML_, 256>>>(out_norm_w, out_norm_b);                     // 7
    hgemm_nt<1><<<dim3(C_ / 128, ML_ / 128), 256>>>(x, out);                  // 8
}